// round 11
// baseline (speedup 1.0000x reference)
#include <cuda_runtime.h>
#include <math.h>

#define NE      50000
#define DIM     64
#define NREL    400
#define NLAYERS 3
#define BS      4
#define NEDGE   400000
#define MAXSLOTS (BS * NE)
#define FULL 0xffffffffu
#define TPB 256
#define WPB (TPB / 32)
#define NLB 64              // layer-pipeline blocks; rest do the bg score

// ---------------- persistent device scratch (static, no allocation) ----------
__device__ float        g_h[MAXSLOTS * DIM];
__device__ float        g_agg[MAXSLOTS * DIM];
__device__ int          g_slotmap[BS * NE];      // slot+1, 0 = free, -1 = claiming
__device__ unsigned int g_mask[NE];              // bit b = (b,node) active
__device__ int          g_elist[BS * NEDGE];     // packed (edge<<2)|b
__device__ int          g_nlist[MAXSLOTS];       // packed (node<<2)|b
__device__ int          g_cnt[8];                // 0 slots, 1 nlist, 2+l edges/layer
__device__ unsigned int g_bar[16];               // barrier counters

struct SMemMsg { float M[DIM * DIM]; float G[DIM * DIM]; float sh[WPB][DIM]; };
struct SMemUpd { float W[2 * DIM * DIM]; float x[WPB][2 * DIM]; };
struct SMemSc  { float2 w[2 * DIM * 32]; float4 te4[WPB][2][DIM]; };
union SMemAll { SMemMsg m; SMemUpd u; SMemSc s; };

// Barrier over `count` blocks (arrivals strictly one per participating block).
__device__ __forceinline__ void bar_n(int i, unsigned count) {
    __syncthreads();
    if (threadIdx.x == 0) {
        __threadfence();
        atomicAdd(&g_bar[i], 1u);
        while (*(volatile unsigned int*)&g_bar[i] < count) __nanosleep(32);
    }
    __syncthreads();
}

// Warp-aggregated append of active (edge,batch) pairs into g_elist.
__device__ __forceinline__ void push4(int base, const unsigned mm[4], int cslot, int lane) {
    int cnt = __popc(mm[0]) + __popc(mm[1]) + __popc(mm[2]) + __popc(mm[3]);
    int x = cnt;
    #pragma unroll
    for (int o = 1; o < 32; o <<= 1) {
        int y = __shfl_up_sync(FULL, x, o);
        if (lane >= o) x += y;
    }
    int warpTotal = __shfl_sync(FULL, x, 31);
    if (warpTotal == 0) return;
    int basePos = 0;
    if (lane == 31) basePos = atomicAdd(&g_cnt[cslot], warpTotal);
    basePos = __shfl_sync(FULL, basePos, 31);
    int pos = basePos + x - cnt;
    #pragma unroll
    for (int j = 0; j < 4; j++) {
        unsigned m = mm[j];
        while (m) {
            int b = __ffs((int)m) - 1;
            m &= m - 1;
            g_elist[pos++] = ((base + j) << 2) | b;
        }
    }
}

__device__ __forceinline__ void scan_layer(const int* __restrict__ esrc, int layer,
                                           int gwarp, int gwarps, int lane) {
    const int CW = NEDGE / 4 / 32;   // 3125
    for (int cw = gwarp; cw < CW; cw += gwarps) {
        int base = (cw * 32 + lane) * 4;
        int4 e4 = *reinterpret_cast<const int4*>(esrc + base);
        unsigned mm[4];
        mm[0] = __ldcg(&g_mask[e4.x]);
        mm[1] = __ldcg(&g_mask[e4.y]);
        mm[2] = __ldcg(&g_mask[e4.z]);
        mm[3] = __ldcg(&g_mask[e4.w]);
        push4(base, mm, 2 + layer, lane);
    }
}

// Background score for 8 nodes per item, written unconditionally to all batches.
__device__ __forceinline__ void bg_score(SMemAll& sm, const float* __restrict__ ent,
                                         float* __restrict__ out,
                                         float rb0, float rb1, float rv0, float rv1,
                                         float b2, int wl, int lane,
                                         int warp0, int warps) {
    const int nBg = NE / 8;   // 6250
    float4* teA = sm.s.te4[wl][0];
    float4* teB = sm.s.te4[wl][1];
    for (int w = warp0; w < nBg; w += warps) {
        int n0 = w * 8;
        float v0 = __ldg(&ent[(n0 + 0) * DIM + lane]);
        float v1 = __ldg(&ent[(n0 + 1) * DIM + lane]);
        float v2 = __ldg(&ent[(n0 + 2) * DIM + lane]);
        float v3 = __ldg(&ent[(n0 + 3) * DIM + lane]);
        float v4 = __ldg(&ent[(n0 + 4) * DIM + lane]);
        float v5 = __ldg(&ent[(n0 + 5) * DIM + lane]);
        float v6 = __ldg(&ent[(n0 + 6) * DIM + lane]);
        float v7 = __ldg(&ent[(n0 + 7) * DIM + lane]);
        float u0 = __ldg(&ent[(n0 + 0) * DIM + lane + 32]);
        float u1 = __ldg(&ent[(n0 + 1) * DIM + lane + 32]);
        float u2 = __ldg(&ent[(n0 + 2) * DIM + lane + 32]);
        float u3 = __ldg(&ent[(n0 + 3) * DIM + lane + 32]);
        float u4 = __ldg(&ent[(n0 + 4) * DIM + lane + 32]);
        float u5 = __ldg(&ent[(n0 + 5) * DIM + lane + 32]);
        float u6 = __ldg(&ent[(n0 + 6) * DIM + lane + 32]);
        float u7 = __ldg(&ent[(n0 + 7) * DIM + lane + 32]);
        teA[lane]      = make_float4(v0, v1, v2, v3);
        teA[lane + 32] = make_float4(u0, u1, u2, u3);
        teB[lane]      = make_float4(v4, v5, v6, v7);
        teB[lane + 32] = make_float4(u4, u5, u6, u7);
        __syncwarp();
        float s0[8], s1[8];
        #pragma unroll
        for (int j = 0; j < 8; j++) { s0[j] = rb0; s1[j] = rb1; }
        #pragma unroll 4
        for (int k = 0; k < DIM; k++) {
            float2 wv = sm.s.w[(DIM + k) * 32 + lane];
            float4 a = teA[k];
            float4 b = teB[k];
            s0[0] = fmaf(a.x, wv.x, s0[0]); s1[0] = fmaf(a.x, wv.y, s1[0]);
            s0[1] = fmaf(a.y, wv.x, s0[1]); s1[1] = fmaf(a.y, wv.y, s1[1]);
            s0[2] = fmaf(a.z, wv.x, s0[2]); s1[2] = fmaf(a.z, wv.y, s1[2]);
            s0[3] = fmaf(a.w, wv.x, s0[3]); s1[3] = fmaf(a.w, wv.y, s1[3]);
            s0[4] = fmaf(b.x, wv.x, s0[4]); s1[4] = fmaf(b.x, wv.y, s1[4]);
            s0[5] = fmaf(b.y, wv.x, s0[5]); s1[5] = fmaf(b.y, wv.y, s1[5]);
            s0[6] = fmaf(b.z, wv.x, s0[6]); s1[6] = fmaf(b.z, wv.y, s1[6]);
            s0[7] = fmaf(b.w, wv.x, s0[7]); s1[7] = fmaf(b.w, wv.y, s1[7]);
        }
        float sc[8];
        #pragma unroll
        for (int j = 0; j < 8; j++) {
            float a = fmaxf(s0[j], 0.f) * rv0 + fmaxf(s1[j], 0.f) * rv1;
            #pragma unroll
            for (int o = 16; o > 0; o >>= 1) a += __shfl_xor_sync(FULL, a, o);
            sc[j] = a + b2;
        }
        if (lane == 0) {
            float4 va = make_float4(sc[0], sc[1], sc[2], sc[3]);
            float4 vb = make_float4(sc[4], sc[5], sc[6], sc[7]);
            #pragma unroll
            for (int b = 0; b < BS; b++) {
                *reinterpret_cast<float4*>(&out[b * NE + n0])     = va;
                *reinterpret_cast<float4*>(&out[b * NE + n0 + 4]) = vb;
            }
        }
        __syncwarp();
    }
}

__global__ void __launch_bounds__(TPB, 2)
k_all(const float* __restrict__ ent, const float* __restrict__ qemb,
      const float* __restrict__ rele, const float* __restrict__ msgW,
      const float* __restrict__ gateW, const float* __restrict__ updW,
      const float* __restrict__ updb, const float* __restrict__ lng,
      const float* __restrict__ lnb, const float* __restrict__ sW1,
      const float* __restrict__ sb1, const float* __restrict__ sW2,
      const float* __restrict__ sb2, const int* __restrict__ source,
      const int* __restrict__ qrel, const int* __restrict__ esrc,
      const int* __restrict__ etgt, const int* __restrict__ erel,
      float* __restrict__ out) {
    __shared__ SMemAll sm;
    const int tid  = threadIdx.x;
    const int lane = tid & 31;
    const int wl   = tid >> 5;
    const int bid  = blockIdx.x;
    const int nb   = gridDim.x;
    const int nlb  = min(NLB, nb);          // layer-pipeline blocks
    const int pbg  = nb - nlb;              // bg-score blocks (may be 0)
    const bool isLayer = bid < nlb;
    const int gthreads = nb * TPB;
    const int gwarps   = gthreads >> 5;
    const int gwarp    = bid * WPB + wl;
    const int gt       = bid * TPB + tid;
    const int lwarps   = nlb * WPB;
    const int lwarp    = gwarp;             // valid for layer blocks only

    // ---------------- P0 (ALL blocks): zero slotmap+mask ∥ scan layer-0 -------
    {
        int4 z = make_int4(0, 0, 0, 0);
        for (int j = gt; j < BS * NE / 4; j += gthreads) ((int4*)g_slotmap)[j] = z;
        for (int j = gt; j < NE / 4; j += gthreads) ((int4*)g_mask)[j] = z;

        int s0 = __ldg(&source[0]), s1 = __ldg(&source[1]);
        int s2 = __ldg(&source[2]), s3 = __ldg(&source[3]);
        const int CW = NEDGE / 4 / 32;
        for (int cw = gwarp; cw < CW; cw += gwarps) {
            int base = (cw * 32 + lane) * 4;
            int4 e4 = *reinterpret_cast<const int4*>(esrc + base);
            unsigned mm[4];
            mm[0] = (unsigned)(e4.x == s0) | ((unsigned)(e4.x == s1) << 1) |
                    ((unsigned)(e4.x == s2) << 2) | ((unsigned)(e4.x == s3) << 3);
            mm[1] = (unsigned)(e4.y == s0) | ((unsigned)(e4.y == s1) << 1) |
                    ((unsigned)(e4.y == s2) << 2) | ((unsigned)(e4.y == s3) << 3);
            mm[2] = (unsigned)(e4.z == s0) | ((unsigned)(e4.z == s1) << 1) |
                    ((unsigned)(e4.z == s2) << 2) | ((unsigned)(e4.z == s3) << 3);
            mm[3] = (unsigned)(e4.w == s0) | ((unsigned)(e4.w == s1) << 1) |
                    ((unsigned)(e4.w == s2) << 2) | ((unsigned)(e4.w == s3) << 3);
            push4(base, mm, 2, lane);
        }
    }
    bar_n(0, nb);

    // ---------------- bg-score blocks: dense score, then join -----------------
    if (!isLayer) {
        for (int i = tid; i < 2 * DIM * 32; i += TPB) {
            int k = i >> 5, j = i & 31;
            sm.s.w[i] = make_float2(__ldg(&sW1[k * DIM + j]), __ldg(&sW1[k * DIM + j + 32]));
        }
        __syncthreads();
        float rb0 = __ldg(&sb1[lane]), rb1 = __ldg(&sb1[lane + 32]);
        float rv0 = __ldg(&sW2[lane]), rv1 = __ldg(&sW2[lane + 32]);
        float b2 = __ldg(&sb2[0]);
        bg_score(sm, ent, out, rb0, rb1, rv0, rv1, b2, wl, lane,
                 (bid - nlb) * WPB + wl, pbg * WPB);
        bar_n(8, nb);           // join: bg writes globally visible
        return;                  // layer blocks finish the rest
    }

    // ========================= layer pipeline (nlb blocks) ====================
    // P1: seed the BS source nodes (block 0)
    if (bid == 0) {
        if (wl < BS) {
            int n = __ldg(&source[wl]);
            int r = __ldg(&qrel[wl]);
            if (lane == 0) {
                g_slotmap[wl * NE + n] = wl + 1;
                atomicOr(&g_mask[n], 1u << wl);
                g_nlist[wl] = (n << 2) | wl;
            }
            g_h[wl * DIM + lane]      = __ldg(&ent[n * DIM + lane])      + __ldg(&qemb[r * DIM + lane]);
            g_h[wl * DIM + lane + 32] = __ldg(&ent[n * DIM + lane + 32]) + __ldg(&qemb[r * DIM + lane + 32]);
            g_agg[wl * DIM + lane] = 0.f;
            g_agg[wl * DIM + lane + 32] = 0.f;
        }
        if (tid == 0) { g_cnt[0] = BS; g_cnt[1] = BS; }
    }
    bar_n(1, nlb);

    for (int l = 0; l < NLAYERS; l++) {
        // ---- msg(l) ----
        {
            int total = __ldcg(&g_cnt[2 + l]);
            int pb = min(nlb, max(1, (total + WPB - 1) / WPB));
            if (bid < pb) {
                for (int i = tid; i < DIM * DIM; i += TPB) {
                    sm.m.M[i] = __ldg(&msgW[l * DIM * DIM + i]);
                    sm.m.G[i] = __ldg(&gateW[l * DIM * DIM + i]);
                }
                __syncthreads();
                for (int idx = bid * WPB + wl; idx < total; idx += pb * WPB) {
                    int p = __ldcg(&g_elist[idx]);
                    int e = p >> 2, b = p & 3;
                    int s = __ldg(&esrc[e]), t = __ldg(&etgt[e]), r = __ldg(&erel[e]);
                    int ss = __ldcg(&g_slotmap[b * NE + s]) - 1;

                    int* sp = &g_slotmap[b * NE + t];
                    int cur;
                    if (lane == 0) cur = atomicCAS(sp, 0, -1);
                    cur = __shfl_sync(FULL, cur, 0);
                    int ts;
                    if (cur == 0) {
                        int slot;
                        if (lane == 0) slot = atomicAdd(&g_cnt[0], 1);
                        slot = __shfl_sync(FULL, slot, 0);
                        g_h[slot * DIM + lane] = 0.f;       g_h[slot * DIM + lane + 32] = 0.f;
                        g_agg[slot * DIM + lane] = 0.f;     g_agg[slot * DIM + lane + 32] = 0.f;
                        __syncwarp();
                        __threadfence();
                        if (lane == 0) {
                            int ni = atomicAdd(&g_cnt[1], 1);
                            g_nlist[ni] = (t << 2) | b;
                            atomicOr(&g_mask[t], 1u << b);
                            atomicExch(sp, slot + 1);
                        }
                        ts = slot;
                    } else if (cur > 0) {
                        ts = cur - 1;
                    } else {
                        if (lane == 0) { do { cur = atomicAdd(sp, 0); } while (cur <= 0); }
                        cur = __shfl_sync(FULL, cur, 0);
                        ts = cur - 1;
                    }

                    sm.m.sh[wl][lane]      = __ldcg(&g_h[ss * DIM + lane]);
                    sm.m.sh[wl][lane + 32] = __ldcg(&g_h[ss * DIM + lane + 32]);
                    __syncwarp();
                    float m0 = 0.f, m1 = 0.f, q0 = 0.f, q1 = 0.f;
                    #pragma unroll 8
                    for (int k = 0; k < DIM; k++) {
                        float hk = sm.m.sh[wl][k];
                        m0 = fmaf(hk, sm.m.M[k * DIM + lane],      m0);
                        m1 = fmaf(hk, sm.m.M[k * DIM + lane + 32], m1);
                        q0 = fmaf(hk, sm.m.G[k * DIM + lane],      q0);
                        q1 = fmaf(hk, sm.m.G[k * DIM + lane + 32], q1);
                    }
                    const float* rr = rele + (size_t)(l * NREL + r) * DIM;
                    float v0 = __ldg(&rr[lane])      * m0 * (1.f / (1.f + expf(-q0)));
                    float v1 = __ldg(&rr[lane + 32]) * m1 * (1.f / (1.f + expf(-q1)));
                    atomicAdd(&g_agg[ts * DIM + lane],      v0);
                    atomicAdd(&g_agg[ts * DIM + lane + 32], v1);
                    __syncwarp();
                }
            }
        }
        bar_n(2 + 2 * l, nlb);

        // ---- scan(l+1) (layer warps) ----
        if (l + 1 < NLAYERS) scan_layer(esrc, l + 1, lwarp, lwarps, lane);

        // ---- update(l) ----
        {
            int total = __ldcg(&g_cnt[1]);
            int pb = min(nlb, max(1, (total + WPB - 1) / WPB));
            if (bid < pb) {
                for (int i = tid; i < 2 * DIM * DIM; i += TPB)
                    sm.u.W[i] = __ldg(&updW[l * 2 * DIM * DIM + i]);
                __syncthreads();
                float ub0 = __ldg(&updb[l * DIM + lane]), ub1 = __ldg(&updb[l * DIM + lane + 32]);
                float lg0 = __ldg(&lng[l * DIM + lane]),  lg1 = __ldg(&lng[l * DIM + lane + 32]);
                float lb0 = __ldg(&lnb[l * DIM + lane]),  lb1 = __ldg(&lnb[l * DIM + lane + 32]);
                for (int idx = bid * WPB + wl; idx < total; idx += pb * WPB) {
                    int p = __ldcg(&g_nlist[idx]);
                    int n = p >> 2, b = p & 3;
                    int slot = __ldcg(&g_slotmap[b * NE + n]) - 1;
                    float h0 = __ldcg(&g_h[slot * DIM + lane]);
                    float h1 = __ldcg(&g_h[slot * DIM + lane + 32]);
                    float a0 = __ldcg(&g_agg[slot * DIM + lane]);
                    float a1 = __ldcg(&g_agg[slot * DIM + lane + 32]);
                    sm.u.x[wl][lane] = h0;      sm.u.x[wl][lane + 32] = h1;
                    sm.u.x[wl][64 + lane] = a0; sm.u.x[wl][96 + lane] = a1;
                    __syncwarp();
                    float u0 = ub0, u1 = ub1;
                    #pragma unroll 8
                    for (int k = 0; k < 2 * DIM; k++) {
                        float xk = sm.u.x[wl][k];
                        u0 = fmaf(xk, sm.u.W[k * DIM + lane],      u0);
                        u1 = fmaf(xk, sm.u.W[k * DIM + lane + 32], u1);
                    }
                    u0 = fmaxf(u0, 0.f); u1 = fmaxf(u1, 0.f);
                    float x0 = h0 + u0, x1 = h1 + u1;
                    float sums = x0 + x1;
                    #pragma unroll
                    for (int o = 16; o > 0; o >>= 1) sums += __shfl_xor_sync(FULL, sums, o);
                    float mean = sums * (1.f / 64.f);
                    float d0 = x0 - mean, d1 = x1 - mean;
                    float v = d0 * d0 + d1 * d1;
                    #pragma unroll
                    for (int o = 16; o > 0; o >>= 1) v += __shfl_xor_sync(FULL, v, o);
                    float inv = rsqrtf(v * (1.f / 64.f) + 1e-5f);
                    g_h[slot * DIM + lane]      = d0 * inv * lg0 + lb0;
                    g_h[slot * DIM + lane + 32] = d1 * inv * lg1 + lb1;
                    g_agg[slot * DIM + lane] = 0.f;
                    g_agg[slot * DIM + lane + 32] = 0.f;
                    __syncwarp();
                }
            }
        }
        bar_n(3 + 2 * l, nlb);
    }

    // ---------------- load score weights, optional bg fallback ----------------
    {
        for (int i = tid; i < 2 * DIM * 32; i += TPB) {
            int k = i >> 5, j = i & 31;
            sm.s.w[i] = make_float2(__ldg(&sW1[k * DIM + j]), __ldg(&sW1[k * DIM + j + 32]));
        }
        __syncthreads();
        float rb0 = __ldg(&sb1[lane]), rb1 = __ldg(&sb1[lane + 32]);
        float rv0 = __ldg(&sW2[lane]), rv1 = __ldg(&sW2[lane + 32]);
        float b2 = __ldg(&sb2[0]);

        if (pbg == 0) {   // no bg pool: layer blocks do the dense score too
            bg_score(sm, ent, out, rb0, rb1, rv0, rv1, b2, wl, lane, lwarp, lwarps);
        }
        bar_n(8, nb);     // join with bg blocks: all bg writes visible

        // ---- active overwrite pass: true score for active (b,n) --------------
        int nAct = __ldcg(&g_cnt[1]);
        float4* teA = sm.s.te4[wl][0];
        float* tep = reinterpret_cast<float*>(teA);
        for (int idx = lwarp; idx < nAct; idx += lwarps) {
            int p = __ldcg(&g_nlist[idx]);
            int n = p >> 2, b = p & 3;
            int slot = __ldcg(&g_slotmap[b * NE + n]) - 1;
            tep[lane]      = __ldcg(&g_h[slot * DIM + lane]);
            tep[lane + 32] = __ldcg(&g_h[slot * DIM + lane + 32]);
            tep[64 + lane] = __ldg(&ent[n * DIM + lane]);
            tep[96 + lane] = __ldg(&ent[n * DIM + lane + 32]);
            __syncwarp();
            float s0 = rb0, s1 = rb1;
            #pragma unroll 8
            for (int k = 0; k < 2 * DIM; k++) {
                float xk = tep[k];
                float2 wv = sm.s.w[k * 32 + lane];
                s0 = fmaf(xk, wv.x, s0);
                s1 = fmaf(xk, wv.y, s1);
            }
            float a = fmaxf(s0, 0.f) * rv0 + fmaxf(s1, 0.f) * rv1;
            #pragma unroll
            for (int o = 16; o > 0; o >>= 1) a += __shfl_xor_sync(FULL, a, o);
            if (lane == 0) out[b * NE + n] = a + b2;
            __syncwarp();
        }
    }

    // ---------------- pre-epilogue barrier (layer blocks) + cleanup -----------
    __syncthreads();
    if (tid == 0) {
        __threadfence();
        atomicAdd(&g_bar[9], 1u);
    }
    if (bid == 0) {
        if (tid == 0) {
            while (*(volatile unsigned int*)&g_bar[9] < (unsigned)nlb) __nanosleep(32);
        }
        __syncthreads();
        int total = __ldcg(&g_cnt[1]);
        for (int i = tid; i < total; i += TPB) {
            int p = __ldcg(&g_nlist[i]);
            int n = p >> 2, b = p & 3;
            g_slotmap[b * NE + n] = 0;
            g_mask[n] = 0u;
        }
        __syncthreads();
        if (tid < 16) g_bar[tid] = 0u;
        if (tid < 8)  g_cnt[tid] = 0;
    }
}

extern "C" void kernel_launch(void* const* d_in, const int* in_sizes, int n_in,
                              void* d_out, int out_size) {
    const float* ent   = (const float*)d_in[0];
    const float* qemb  = (const float*)d_in[1];
    const float* rele  = (const float*)d_in[2];
    const float* msgW  = (const float*)d_in[3];
    const float* gateW = (const float*)d_in[4];
    const float* updW  = (const float*)d_in[5];
    const float* updb  = (const float*)d_in[6];
    const float* lng   = (const float*)d_in[7];
    const float* lnb   = (const float*)d_in[8];
    const float* sW1   = (const float*)d_in[9];
    const float* sb1   = (const float*)d_in[10];
    const float* sW2   = (const float*)d_in[11];
    const float* sb2   = (const float*)d_in[12];
    const int* source  = (const int*)d_in[13];
    const int* qrel    = (const int*)d_in[14];
    const int* esrc    = (const int*)d_in[15];
    const int* etgt    = (const int*)d_in[16];
    const int* erel    = (const int*)d_in[17];
    float* out = (float*)d_out;

    int dev = 0;
    cudaGetDevice(&dev);
    int sms = 0;
    cudaDeviceGetAttribute(&sms, cudaDevAttrMultiProcessorCount, dev);
    int maxb = 0;
    cudaOccupancyMaxActiveBlocksPerMultiprocessor(&maxb, k_all, TPB, 0);
    if (maxb < 1) maxb = 1;
    int grid = sms * maxb;

    k_all<<<grid, TPB>>>(ent, qemb, rele, msgW, gateW, updW, updb, lng, lnb,
                         sW1, sb1, sW2, sb2, source, qrel, esrc, etgt, erel, out);
}

// round 12
// speedup vs baseline: 1.3793x; 1.3793x over previous
#include <cuda_runtime.h>
#include <math.h>

#define NE      50000
#define DIM     64
#define NREL    400
#define NLAYERS 3
#define BS      4
#define NEDGE   400000
#define MAXSLOTS (BS * NE)
#define FULL 0xffffffffu
#define TPB 256
#define WPB (TPB / 32)

// ---------------- persistent device scratch (static, no allocation) ----------
__device__ float        g_h[MAXSLOTS * DIM];
__device__ float        g_agg[MAXSLOTS * DIM];
__device__ int          g_slotmap[BS * NE];      // slot+1, 0 = free, -1 = claiming
__device__ unsigned int g_mask[NE];              // bit b = (b,node) active
__device__ int          g_elist[BS * NEDGE];     // packed (edge<<2)|b
__device__ int          g_nlist[MAXSLOTS];       // packed (node<<2)|b
__device__ int          g_cnt[8];                // 0 slots, 1 nlist, 2+l edges/layer
__device__ unsigned int g_bar[16];               // barrier counters

struct SMemMsg { float M[DIM * DIM]; float G[DIM * DIM]; float sh[WPB][DIM]; };
struct SMemUpd { float W[2 * DIM * DIM]; float x[WPB][2 * DIM]; };
struct SMemSc  { float2 w[2 * DIM * 32]; float4 te4[WPB][2][DIM]; };
union SMemAll { SMemMsg m; SMemUpd u; SMemSc s; };

// Barrier over `count` blocks (arrivals strictly one per participating block).
__device__ __forceinline__ void bar_n(int i, unsigned count) {
    __syncthreads();
    if (threadIdx.x == 0) {
        __threadfence();
        atomicAdd(&g_bar[i], 1u);
        while (*(volatile unsigned int*)&g_bar[i] < count) __nanosleep(128);
    }
    __syncthreads();
}

// Warp-aggregated append of active (edge,batch) pairs into g_elist.
__device__ __forceinline__ void push4(int base, const unsigned mm[4], int cslot, int lane) {
    int cnt = __popc(mm[0]) + __popc(mm[1]) + __popc(mm[2]) + __popc(mm[3]);
    int x = cnt;
    #pragma unroll
    for (int o = 1; o < 32; o <<= 1) {
        int y = __shfl_up_sync(FULL, x, o);
        if (lane >= o) x += y;
    }
    int warpTotal = __shfl_sync(FULL, x, 31);
    if (warpTotal == 0) return;
    int basePos = 0;
    if (lane == 31) basePos = atomicAdd(&g_cnt[cslot], warpTotal);
    basePos = __shfl_sync(FULL, basePos, 31);
    int pos = basePos + x - cnt;
    #pragma unroll
    for (int j = 0; j < 4; j++) {
        unsigned m = mm[j];
        while (m) {
            int b = __ffs((int)m) - 1;
            m &= m - 1;
            g_elist[pos++] = ((base + j) << 2) | b;
        }
    }
}

__device__ __forceinline__ void scan_layer(const int* __restrict__ esrc, int layer,
                                           int gwarp, int gwarps, int lane) {
    const int CW = NEDGE / 4 / 32;   // 3125
    for (int cw = gwarp; cw < CW; cw += gwarps) {
        int base = (cw * 32 + lane) * 4;
        int4 e4 = *reinterpret_cast<const int4*>(esrc + base);
        unsigned mm[4];
        mm[0] = __ldcg(&g_mask[e4.x]);
        mm[1] = __ldcg(&g_mask[e4.y]);
        mm[2] = __ldcg(&g_mask[e4.z]);
        mm[3] = __ldcg(&g_mask[e4.w]);
        push4(base, mm, 2 + layer, lane);
    }
}

// Background score for 8 nodes per item, written unconditionally to all batches.
__device__ __forceinline__ void bg_score(SMemAll& sm, const float* __restrict__ ent,
                                         float* __restrict__ out,
                                         float rb0, float rb1, float rv0, float rv1,
                                         float b2, int wl, int lane,
                                         int warp0, int warps) {
    const int nBg = NE / 8;   // 6250
    float4* teA = sm.s.te4[wl][0];
    float4* teB = sm.s.te4[wl][1];
    for (int w = warp0; w < nBg; w += warps) {
        int n0 = w * 8;
        float v0 = __ldg(&ent[(n0 + 0) * DIM + lane]);
        float v1 = __ldg(&ent[(n0 + 1) * DIM + lane]);
        float v2 = __ldg(&ent[(n0 + 2) * DIM + lane]);
        float v3 = __ldg(&ent[(n0 + 3) * DIM + lane]);
        float v4 = __ldg(&ent[(n0 + 4) * DIM + lane]);
        float v5 = __ldg(&ent[(n0 + 5) * DIM + lane]);
        float v6 = __ldg(&ent[(n0 + 6) * DIM + lane]);
        float v7 = __ldg(&ent[(n0 + 7) * DIM + lane]);
        float u0 = __ldg(&ent[(n0 + 0) * DIM + lane + 32]);
        float u1 = __ldg(&ent[(n0 + 1) * DIM + lane + 32]);
        float u2 = __ldg(&ent[(n0 + 2) * DIM + lane + 32]);
        float u3 = __ldg(&ent[(n0 + 3) * DIM + lane + 32]);
        float u4 = __ldg(&ent[(n0 + 4) * DIM + lane + 32]);
        float u5 = __ldg(&ent[(n0 + 5) * DIM + lane + 32]);
        float u6 = __ldg(&ent[(n0 + 6) * DIM + lane + 32]);
        float u7 = __ldg(&ent[(n0 + 7) * DIM + lane + 32]);
        teA[lane]      = make_float4(v0, v1, v2, v3);
        teA[lane + 32] = make_float4(u0, u1, u2, u3);
        teB[lane]      = make_float4(v4, v5, v6, v7);
        teB[lane + 32] = make_float4(u4, u5, u6, u7);
        __syncwarp();
        float s0[8], s1[8];
        #pragma unroll
        for (int j = 0; j < 8; j++) { s0[j] = rb0; s1[j] = rb1; }
        #pragma unroll 4
        for (int k = 0; k < DIM; k++) {
            float2 wv = sm.s.w[(DIM + k) * 32 + lane];
            float4 a = teA[k];
            float4 b = teB[k];
            s0[0] = fmaf(a.x, wv.x, s0[0]); s1[0] = fmaf(a.x, wv.y, s1[0]);
            s0[1] = fmaf(a.y, wv.x, s0[1]); s1[1] = fmaf(a.y, wv.y, s1[1]);
            s0[2] = fmaf(a.z, wv.x, s0[2]); s1[2] = fmaf(a.z, wv.y, s1[2]);
            s0[3] = fmaf(a.w, wv.x, s0[3]); s1[3] = fmaf(a.w, wv.y, s1[3]);
            s0[4] = fmaf(b.x, wv.x, s0[4]); s1[4] = fmaf(b.x, wv.y, s1[4]);
            s0[5] = fmaf(b.y, wv.x, s0[5]); s1[5] = fmaf(b.y, wv.y, s1[5]);
            s0[6] = fmaf(b.z, wv.x, s0[6]); s1[6] = fmaf(b.z, wv.y, s1[6]);
            s0[7] = fmaf(b.w, wv.x, s0[7]); s1[7] = fmaf(b.w, wv.y, s1[7]);
        }
        float sc[8];
        #pragma unroll
        for (int j = 0; j < 8; j++) {
            float a = fmaxf(s0[j], 0.f) * rv0 + fmaxf(s1[j], 0.f) * rv1;
            #pragma unroll
            for (int o = 16; o > 0; o >>= 1) a += __shfl_xor_sync(FULL, a, o);
            sc[j] = a + b2;
        }
        if (lane == 0) {
            float4 va = make_float4(sc[0], sc[1], sc[2], sc[3]);
            float4 vb = make_float4(sc[4], sc[5], sc[6], sc[7]);
            #pragma unroll
            for (int b = 0; b < BS; b++) {
                *reinterpret_cast<float4*>(&out[b * NE + n0])     = va;
                *reinterpret_cast<float4*>(&out[b * NE + n0 + 4]) = vb;
            }
        }
        __syncwarp();
    }
}

__global__ void __launch_bounds__(TPB, 2)
k_all(const float* __restrict__ ent, const float* __restrict__ qemb,
      const float* __restrict__ rele, const float* __restrict__ msgW,
      const float* __restrict__ gateW, const float* __restrict__ updW,
      const float* __restrict__ updb, const float* __restrict__ lng,
      const float* __restrict__ lnb, const float* __restrict__ sW1,
      const float* __restrict__ sb1, const float* __restrict__ sW2,
      const float* __restrict__ sb2, const int* __restrict__ source,
      const int* __restrict__ qrel, const int* __restrict__ esrc,
      const int* __restrict__ etgt, const int* __restrict__ erel,
      float* __restrict__ out) {
    __shared__ SMemAll sm;
    const int tid  = threadIdx.x;
    const int lane = tid & 31;
    const int wl   = tid >> 5;
    const int bid  = blockIdx.x;
    const int nb   = gridDim.x;
    const int pbg  = nb / 3;                // bg-score blocks (148 of 444)
    const int nlb  = nb - pbg;              // layer-pipeline blocks (296)
    const bool isLayer = bid < nlb;
    const int gthreads = nb * TPB;
    const int gwarps   = gthreads >> 5;
    const int gwarp    = bid * WPB + wl;
    const int gt       = bid * TPB + tid;
    const int lwarps   = nlb * WPB;
    const int lwarp    = gwarp;             // valid for layer blocks only

    // ---------------- P0 (ALL blocks): zero slotmap+mask ∥ scan layer-0 -------
    {
        int4 z = make_int4(0, 0, 0, 0);
        for (int j = gt; j < BS * NE / 4; j += gthreads) ((int4*)g_slotmap)[j] = z;
        for (int j = gt; j < NE / 4; j += gthreads) ((int4*)g_mask)[j] = z;

        int s0 = __ldg(&source[0]), s1 = __ldg(&source[1]);
        int s2 = __ldg(&source[2]), s3 = __ldg(&source[3]);
        const int CW = NEDGE / 4 / 32;
        for (int cw = gwarp; cw < CW; cw += gwarps) {
            int base = (cw * 32 + lane) * 4;
            int4 e4 = *reinterpret_cast<const int4*>(esrc + base);
            unsigned mm[4];
            mm[0] = (unsigned)(e4.x == s0) | ((unsigned)(e4.x == s1) << 1) |
                    ((unsigned)(e4.x == s2) << 2) | ((unsigned)(e4.x == s3) << 3);
            mm[1] = (unsigned)(e4.y == s0) | ((unsigned)(e4.y == s1) << 1) |
                    ((unsigned)(e4.y == s2) << 2) | ((unsigned)(e4.y == s3) << 3);
            mm[2] = (unsigned)(e4.z == s0) | ((unsigned)(e4.z == s1) << 1) |
                    ((unsigned)(e4.z == s2) << 2) | ((unsigned)(e4.z == s3) << 3);
            mm[3] = (unsigned)(e4.w == s0) | ((unsigned)(e4.w == s1) << 1) |
                    ((unsigned)(e4.w == s2) << 2) | ((unsigned)(e4.w == s3) << 3);
            push4(base, mm, 2, lane);
        }
    }
    bar_n(0, nb);

    // ---------------- bg-score blocks: dense score, then join -----------------
    if (!isLayer) {
        for (int i = tid; i < 2 * DIM * 32; i += TPB) {
            int k = i >> 5, j = i & 31;
            sm.s.w[i] = make_float2(__ldg(&sW1[k * DIM + j]), __ldg(&sW1[k * DIM + j + 32]));
        }
        __syncthreads();
        float rb0 = __ldg(&sb1[lane]), rb1 = __ldg(&sb1[lane + 32]);
        float rv0 = __ldg(&sW2[lane]), rv1 = __ldg(&sW2[lane + 32]);
        float b2 = __ldg(&sb2[0]);
        bg_score(sm, ent, out, rb0, rb1, rv0, rv1, b2, wl, lane,
                 (bid - nlb) * WPB + wl, pbg * WPB);
        bar_n(8, nb);           // join: bg writes globally visible
        return;                  // layer blocks finish the rest
    }

    // ========================= layer pipeline (nlb blocks) ====================
    // P1: seed the BS source nodes (block 0)
    if (bid == 0) {
        if (wl < BS) {
            int n = __ldg(&source[wl]);
            int r = __ldg(&qrel[wl]);
            if (lane == 0) {
                g_slotmap[wl * NE + n] = wl + 1;
                atomicOr(&g_mask[n], 1u << wl);
                g_nlist[wl] = (n << 2) | wl;
            }
            g_h[wl * DIM + lane]      = __ldg(&ent[n * DIM + lane])      + __ldg(&qemb[r * DIM + lane]);
            g_h[wl * DIM + lane + 32] = __ldg(&ent[n * DIM + lane + 32]) + __ldg(&qemb[r * DIM + lane + 32]);
            g_agg[wl * DIM + lane] = 0.f;
            g_agg[wl * DIM + lane + 32] = 0.f;
        }
        if (tid == 0) { g_cnt[0] = BS; g_cnt[1] = BS; }
    }
    bar_n(1, nlb);

    for (int l = 0; l < NLAYERS; l++) {
        // ---- msg(l) ----
        {
            int total = __ldcg(&g_cnt[2 + l]);
            int pb = min(nlb, max(1, (total + WPB - 1) / WPB));
            if (bid < pb) {
                for (int i = tid; i < DIM * DIM; i += TPB) {
                    sm.m.M[i] = __ldg(&msgW[l * DIM * DIM + i]);
                    sm.m.G[i] = __ldg(&gateW[l * DIM * DIM + i]);
                }
                __syncthreads();
                for (int idx = bid * WPB + wl; idx < total; idx += pb * WPB) {
                    int p = __ldcg(&g_elist[idx]);
                    int e = p >> 2, b = p & 3;
                    int s = __ldg(&esrc[e]), t = __ldg(&etgt[e]), r = __ldg(&erel[e]);
                    int ss = __ldcg(&g_slotmap[b * NE + s]) - 1;

                    int* sp = &g_slotmap[b * NE + t];
                    int cur;
                    if (lane == 0) cur = atomicCAS(sp, 0, -1);
                    cur = __shfl_sync(FULL, cur, 0);
                    int ts;
                    if (cur == 0) {
                        int slot;
                        if (lane == 0) slot = atomicAdd(&g_cnt[0], 1);
                        slot = __shfl_sync(FULL, slot, 0);
                        g_h[slot * DIM + lane] = 0.f;       g_h[slot * DIM + lane + 32] = 0.f;
                        g_agg[slot * DIM + lane] = 0.f;     g_agg[slot * DIM + lane + 32] = 0.f;
                        __syncwarp();
                        __threadfence();
                        if (lane == 0) {
                            int ni = atomicAdd(&g_cnt[1], 1);
                            g_nlist[ni] = (t << 2) | b;
                            atomicOr(&g_mask[t], 1u << b);
                            atomicExch(sp, slot + 1);
                        }
                        ts = slot;
                    } else if (cur > 0) {
                        ts = cur - 1;
                    } else {
                        if (lane == 0) { do { cur = atomicAdd(sp, 0); } while (cur <= 0); }
                        cur = __shfl_sync(FULL, cur, 0);
                        ts = cur - 1;
                    }

                    sm.m.sh[wl][lane]      = __ldcg(&g_h[ss * DIM + lane]);
                    sm.m.sh[wl][lane + 32] = __ldcg(&g_h[ss * DIM + lane + 32]);
                    __syncwarp();
                    float m0 = 0.f, m1 = 0.f, q0 = 0.f, q1 = 0.f;
                    #pragma unroll 8
                    for (int k = 0; k < DIM; k++) {
                        float hk = sm.m.sh[wl][k];
                        m0 = fmaf(hk, sm.m.M[k * DIM + lane],      m0);
                        m1 = fmaf(hk, sm.m.M[k * DIM + lane + 32], m1);
                        q0 = fmaf(hk, sm.m.G[k * DIM + lane],      q0);
                        q1 = fmaf(hk, sm.m.G[k * DIM + lane + 32], q1);
                    }
                    const float* rr = rele + (size_t)(l * NREL + r) * DIM;
                    float v0 = __ldg(&rr[lane])      * m0 * (1.f / (1.f + expf(-q0)));
                    float v1 = __ldg(&rr[lane + 32]) * m1 * (1.f / (1.f + expf(-q1)));
                    atomicAdd(&g_agg[ts * DIM + lane],      v0);
                    atomicAdd(&g_agg[ts * DIM + lane + 32], v1);
                    __syncwarp();
                }
            }
        }
        bar_n(2 + 2 * l, nlb);

        // ---- scan(l+1) (layer warps) ----
        if (l + 1 < NLAYERS) scan_layer(esrc, l + 1, lwarp, lwarps, lane);

        // ---- update(l) ----
        {
            int total = __ldcg(&g_cnt[1]);
            int pb = min(nlb, max(1, (total + WPB - 1) / WPB));
            if (bid < pb) {
                for (int i = tid; i < 2 * DIM * DIM; i += TPB)
                    sm.u.W[i] = __ldg(&updW[l * 2 * DIM * DIM + i]);
                __syncthreads();
                float ub0 = __ldg(&updb[l * DIM + lane]), ub1 = __ldg(&updb[l * DIM + lane + 32]);
                float lg0 = __ldg(&lng[l * DIM + lane]),  lg1 = __ldg(&lng[l * DIM + lane + 32]);
                float lb0 = __ldg(&lnb[l * DIM + lane]),  lb1 = __ldg(&lnb[l * DIM + lane + 32]);
                for (int idx = bid * WPB + wl; idx < total; idx += pb * WPB) {
                    int p = __ldcg(&g_nlist[idx]);
                    int n = p >> 2, b = p & 3;
                    int slot = __ldcg(&g_slotmap[b * NE + n]) - 1;
                    float h0 = __ldcg(&g_h[slot * DIM + lane]);
                    float h1 = __ldcg(&g_h[slot * DIM + lane + 32]);
                    float a0 = __ldcg(&g_agg[slot * DIM + lane]);
                    float a1 = __ldcg(&g_agg[slot * DIM + lane + 32]);
                    sm.u.x[wl][lane] = h0;      sm.u.x[wl][lane + 32] = h1;
                    sm.u.x[wl][64 + lane] = a0; sm.u.x[wl][96 + lane] = a1;
                    __syncwarp();
                    float u0 = ub0, u1 = ub1;
                    #pragma unroll 8
                    for (int k = 0; k < 2 * DIM; k++) {
                        float xk = sm.u.x[wl][k];
                        u0 = fmaf(xk, sm.u.W[k * DIM + lane],      u0);
                        u1 = fmaf(xk, sm.u.W[k * DIM + lane + 32], u1);
                    }
                    u0 = fmaxf(u0, 0.f); u1 = fmaxf(u1, 0.f);
                    float x0 = h0 + u0, x1 = h1 + u1;
                    float sums = x0 + x1;
                    #pragma unroll
                    for (int o = 16; o > 0; o >>= 1) sums += __shfl_xor_sync(FULL, sums, o);
                    float mean = sums * (1.f / 64.f);
                    float d0 = x0 - mean, d1 = x1 - mean;
                    float v = d0 * d0 + d1 * d1;
                    #pragma unroll
                    for (int o = 16; o > 0; o >>= 1) v += __shfl_xor_sync(FULL, v, o);
                    float inv = rsqrtf(v * (1.f / 64.f) + 1e-5f);
                    g_h[slot * DIM + lane]      = d0 * inv * lg0 + lb0;
                    g_h[slot * DIM + lane + 32] = d1 * inv * lg1 + lb1;
                    g_agg[slot * DIM + lane] = 0.f;
                    g_agg[slot * DIM + lane + 32] = 0.f;
                    __syncwarp();
                }
            }
        }
        bar_n(3 + 2 * l, nlb);
    }

    // ---------------- load score weights, optional bg fallback ----------------
    {
        for (int i = tid; i < 2 * DIM * 32; i += TPB) {
            int k = i >> 5, j = i & 31;
            sm.s.w[i] = make_float2(__ldg(&sW1[k * DIM + j]), __ldg(&sW1[k * DIM + j + 32]));
        }
        __syncthreads();
        float rb0 = __ldg(&sb1[lane]), rb1 = __ldg(&sb1[lane + 32]);
        float rv0 = __ldg(&sW2[lane]), rv1 = __ldg(&sW2[lane + 32]);
        float b2 = __ldg(&sb2[0]);

        if (pbg == 0) {   // no bg pool: layer blocks do the dense score too
            bg_score(sm, ent, out, rb0, rb1, rv0, rv1, b2, wl, lane, lwarp, lwarps);
        }
        bar_n(8, nb);     // join with bg blocks: all bg writes visible

        // ---- active overwrite pass: true score for active (b,n) --------------
        int nAct = __ldcg(&g_cnt[1]);
        float4* teA = sm.s.te4[wl][0];
        float* tep = reinterpret_cast<float*>(teA);
        for (int idx = lwarp; idx < nAct; idx += lwarps) {
            int p = __ldcg(&g_nlist[idx]);
            int n = p >> 2, b = p & 3;
            int slot = __ldcg(&g_slotmap[b * NE + n]) - 1;
            tep[lane]      = __ldcg(&g_h[slot * DIM + lane]);
            tep[lane + 32] = __ldcg(&g_h[slot * DIM + lane + 32]);
            tep[64 + lane] = __ldg(&ent[n * DIM + lane]);
            tep[96 + lane] = __ldg(&ent[n * DIM + lane + 32]);
            __syncwarp();
            float s0 = rb0, s1 = rb1;
            #pragma unroll 8
            for (int k = 0; k < 2 * DIM; k++) {
                float xk = tep[k];
                float2 wv = sm.s.w[k * 32 + lane];
                s0 = fmaf(xk, wv.x, s0);
                s1 = fmaf(xk, wv.y, s1);
            }
            float a = fmaxf(s0, 0.f) * rv0 + fmaxf(s1, 0.f) * rv1;
            #pragma unroll
            for (int o = 16; o > 0; o >>= 1) a += __shfl_xor_sync(FULL, a, o);
            if (lane == 0) out[b * NE + n] = a + b2;
            __syncwarp();
        }
    }

    // ---------------- pre-epilogue barrier (layer blocks) + cleanup -----------
    __syncthreads();
    if (tid == 0) {
        __threadfence();
        atomicAdd(&g_bar[9], 1u);
    }
    if (bid == 0) {
        if (tid == 0) {
            while (*(volatile unsigned int*)&g_bar[9] < (unsigned)nlb) __nanosleep(128);
        }
        __syncthreads();
        int total = __ldcg(&g_cnt[1]);
        for (int i = tid; i < total; i += TPB) {
            int p = __ldcg(&g_nlist[i]);
            int n = p >> 2, b = p & 3;
            g_slotmap[b * NE + n] = 0;
            g_mask[n] = 0u;
        }
        __syncthreads();
        if (tid < 16) g_bar[tid] = 0u;
        if (tid < 8)  g_cnt[tid] = 0;
    }
}

extern "C" void kernel_launch(void* const* d_in, const int* in_sizes, int n_in,
                              void* d_out, int out_size) {
    const float* ent   = (const float*)d_in[0];
    const float* qemb  = (const float*)d_in[1];
    const float* rele  = (const float*)d_in[2];
    const float* msgW  = (const float*)d_in[3];
    const float* gateW = (const float*)d_in[4];
    const float* updW  = (const float*)d_in[5];
    const float* updb  = (const float*)d_in[6];
    const float* lng   = (const float*)d_in[7];
    const float* lnb   = (const float*)d_in[8];
    const float* sW1   = (const float*)d_in[9];
    const float* sb1   = (const float*)d_in[10];
    const float* sW2   = (const float*)d_in[11];
    const float* sb2   = (const float*)d_in[12];
    const int* source  = (const int*)d_in[13];
    const int* qrel    = (const int*)d_in[14];
    const int* esrc    = (const int*)d_in[15];
    const int* etgt    = (const int*)d_in[16];
    const int* erel    = (const int*)d_in[17];
    float* out = (float*)d_out;

    int dev = 0;
    cudaGetDevice(&dev);
    int sms = 0;
    cudaDeviceGetAttribute(&sms, cudaDevAttrMultiProcessorCount, dev);
    int maxb = 0;
    cudaOccupancyMaxActiveBlocksPerMultiprocessor(&maxb, k_all, TPB, 0);
    if (maxb < 1) maxb = 1;
    int grid = sms * maxb;

    k_all<<<grid, TPB>>>(ent, qemb, rele, msgW, gateW, updW, updb, lng, lnb,
                         sW1, sb1, sW2, sb2, source, qrel, esrc, etgt, erel, out);
}

// round 13
// speedup vs baseline: 1.3815x; 1.0016x over previous
#include <cuda_runtime.h>
#include <math.h>

#define NE      50000
#define DIM     64
#define NREL    400
#define NLAYERS 3
#define BS      4
#define NEDGE   400000
#define MAXSLOTS (BS * NE)
#define FULL 0xffffffffu
#define TPB 256
#define WPB (TPB / 32)

// ---------------- persistent device scratch (static, no allocation) ----------
// Invariant: slotmap/mask/cnt/bar are ALL-ZERO at kernel entry. Guaranteed by
// the loader on first launch and by the epilogue cleanup on every launch.
__device__ float        g_h[MAXSLOTS * DIM];
__device__ float        g_agg[MAXSLOTS * DIM];
__device__ int          g_slotmap[BS * NE];      // slot+1, 0 = free, -1 = claiming
__device__ unsigned int g_mask[NE];              // bit b = (b,node) active
__device__ int          g_elist[BS * NEDGE];     // packed (edge<<2)|b
__device__ int          g_nlist[MAXSLOTS];       // packed (node<<2)|b
__device__ int          g_cnt[8];                // 0 slots, 1 nlist, 2+l edges/layer
__device__ unsigned int g_bar[16];               // barrier counters

struct SMemMsg { float M[DIM * DIM]; float G[DIM * DIM]; float sh[WPB][DIM]; };
struct SMemUpd { float W[2 * DIM * DIM]; float x[WPB][2 * DIM]; };
struct SMemSc  { float2 w[2 * DIM * 32]; float4 te4[WPB][2][DIM]; };
union SMemAll { SMemMsg m; SMemUpd u; SMemSc s; };

// Barrier over `count` blocks (arrivals strictly one per participating block).
__device__ __forceinline__ void bar_n(int i, unsigned count) {
    __syncthreads();
    if (threadIdx.x == 0) {
        __threadfence();
        atomicAdd(&g_bar[i], 1u);
        while (*(volatile unsigned int*)&g_bar[i] < count) __nanosleep(128);
    }
    __syncthreads();
}

// Warp-aggregated append of active (edge,batch) pairs into g_elist.
__device__ __forceinline__ void push4(int base, const unsigned mm[4], int cslot, int lane) {
    int cnt = __popc(mm[0]) + __popc(mm[1]) + __popc(mm[2]) + __popc(mm[3]);
    int x = cnt;
    #pragma unroll
    for (int o = 1; o < 32; o <<= 1) {
        int y = __shfl_up_sync(FULL, x, o);
        if (lane >= o) x += y;
    }
    int warpTotal = __shfl_sync(FULL, x, 31);
    if (warpTotal == 0) return;
    int basePos = 0;
    if (lane == 31) basePos = atomicAdd(&g_cnt[cslot], warpTotal);
    basePos = __shfl_sync(FULL, basePos, 31);
    int pos = basePos + x - cnt;
    #pragma unroll
    for (int j = 0; j < 4; j++) {
        unsigned m = mm[j];
        while (m) {
            int b = __ffs((int)m) - 1;
            m &= m - 1;
            g_elist[pos++] = ((base + j) << 2) | b;
        }
    }
}

__device__ __forceinline__ void scan_layer(const int* __restrict__ esrc, int layer,
                                           int gwarp, int gwarps, int lane) {
    const int CW = NEDGE / 4 / 32;   // 3125
    for (int cw = gwarp; cw < CW; cw += gwarps) {
        int base = (cw * 32 + lane) * 4;
        int4 e4 = *reinterpret_cast<const int4*>(esrc + base);
        unsigned mm[4];
        mm[0] = __ldcg(&g_mask[e4.x]);
        mm[1] = __ldcg(&g_mask[e4.y]);
        mm[2] = __ldcg(&g_mask[e4.z]);
        mm[3] = __ldcg(&g_mask[e4.w]);
        push4(base, mm, 2 + layer, lane);
    }
}

// Background score for 8 nodes per item, written unconditionally to all batches.
__device__ __forceinline__ void bg_score(SMemAll& sm, const float* __restrict__ ent,
                                         float* __restrict__ out,
                                         float rb0, float rb1, float rv0, float rv1,
                                         float b2, int wl, int lane,
                                         int warp0, int warps) {
    const int nBg = NE / 8;   // 6250
    float4* teA = sm.s.te4[wl][0];
    float4* teB = sm.s.te4[wl][1];
    for (int w = warp0; w < nBg; w += warps) {
        int n0 = w * 8;
        float v0 = __ldg(&ent[(n0 + 0) * DIM + lane]);
        float v1 = __ldg(&ent[(n0 + 1) * DIM + lane]);
        float v2 = __ldg(&ent[(n0 + 2) * DIM + lane]);
        float v3 = __ldg(&ent[(n0 + 3) * DIM + lane]);
        float v4 = __ldg(&ent[(n0 + 4) * DIM + lane]);
        float v5 = __ldg(&ent[(n0 + 5) * DIM + lane]);
        float v6 = __ldg(&ent[(n0 + 6) * DIM + lane]);
        float v7 = __ldg(&ent[(n0 + 7) * DIM + lane]);
        float u0 = __ldg(&ent[(n0 + 0) * DIM + lane + 32]);
        float u1 = __ldg(&ent[(n0 + 1) * DIM + lane + 32]);
        float u2 = __ldg(&ent[(n0 + 2) * DIM + lane + 32]);
        float u3 = __ldg(&ent[(n0 + 3) * DIM + lane + 32]);
        float u4 = __ldg(&ent[(n0 + 4) * DIM + lane + 32]);
        float u5 = __ldg(&ent[(n0 + 5) * DIM + lane + 32]);
        float u6 = __ldg(&ent[(n0 + 6) * DIM + lane + 32]);
        float u7 = __ldg(&ent[(n0 + 7) * DIM + lane + 32]);
        teA[lane]      = make_float4(v0, v1, v2, v3);
        teA[lane + 32] = make_float4(u0, u1, u2, u3);
        teB[lane]      = make_float4(v4, v5, v6, v7);
        teB[lane + 32] = make_float4(u4, u5, u6, u7);
        __syncwarp();
        float s0[8], s1[8];
        #pragma unroll
        for (int j = 0; j < 8; j++) { s0[j] = rb0; s1[j] = rb1; }
        #pragma unroll 4
        for (int k = 0; k < DIM; k++) {
            float2 wv = sm.s.w[(DIM + k) * 32 + lane];
            float4 a = teA[k];
            float4 b = teB[k];
            s0[0] = fmaf(a.x, wv.x, s0[0]); s1[0] = fmaf(a.x, wv.y, s1[0]);
            s0[1] = fmaf(a.y, wv.x, s0[1]); s1[1] = fmaf(a.y, wv.y, s1[1]);
            s0[2] = fmaf(a.z, wv.x, s0[2]); s1[2] = fmaf(a.z, wv.y, s1[2]);
            s0[3] = fmaf(a.w, wv.x, s0[3]); s1[3] = fmaf(a.w, wv.y, s1[3]);
            s0[4] = fmaf(b.x, wv.x, s0[4]); s1[4] = fmaf(b.x, wv.y, s1[4]);
            s0[5] = fmaf(b.y, wv.x, s0[5]); s1[5] = fmaf(b.y, wv.y, s1[5]);
            s0[6] = fmaf(b.z, wv.x, s0[6]); s1[6] = fmaf(b.z, wv.y, s1[6]);
            s0[7] = fmaf(b.w, wv.x, s0[7]); s1[7] = fmaf(b.w, wv.y, s1[7]);
        }
        float sc[8];
        #pragma unroll
        for (int j = 0; j < 8; j++) {
            float a = fmaxf(s0[j], 0.f) * rv0 + fmaxf(s1[j], 0.f) * rv1;
            #pragma unroll
            for (int o = 16; o > 0; o >>= 1) a += __shfl_xor_sync(FULL, a, o);
            sc[j] = a + b2;
        }
        if (lane == 0) {
            float4 va = make_float4(sc[0], sc[1], sc[2], sc[3]);
            float4 vb = make_float4(sc[4], sc[5], sc[6], sc[7]);
            #pragma unroll
            for (int b = 0; b < BS; b++) {
                *reinterpret_cast<float4*>(&out[b * NE + n0])     = va;
                *reinterpret_cast<float4*>(&out[b * NE + n0 + 4]) = vb;
            }
        }
        __syncwarp();
    }
}

__global__ void __launch_bounds__(TPB, 2)
k_all(const float* __restrict__ ent, const float* __restrict__ qemb,
      const float* __restrict__ rele, const float* __restrict__ msgW,
      const float* __restrict__ gateW, const float* __restrict__ updW,
      const float* __restrict__ updb, const float* __restrict__ lng,
      const float* __restrict__ lnb, const float* __restrict__ sW1,
      const float* __restrict__ sb1, const float* __restrict__ sW2,
      const float* __restrict__ sb2, const int* __restrict__ source,
      const int* __restrict__ qrel, const int* __restrict__ esrc,
      const int* __restrict__ etgt, const int* __restrict__ erel,
      float* __restrict__ out) {
    __shared__ SMemAll sm;
    const int tid  = threadIdx.x;
    const int lane = tid & 31;
    const int wl   = tid >> 5;
    const int bid  = blockIdx.x;
    const int nb   = gridDim.x;
    const int pbg  = nb / 3;                // bg-score blocks
    const int nlb  = nb - pbg;              // layer-pipeline blocks
    const bool isLayer = bid < nlb;
    const int gthreads = nb * TPB;
    const int gwarps   = gthreads >> 5;
    const int gwarp    = bid * WPB + wl;
    const int lwarps   = nlb * WPB;
    const int lwarp    = gwarp;             // valid for layer blocks only

    // ---------------- P0: scan layer-0 + seed + weight preload ----------------
    // (No zeroing: slotmap/mask are zero at entry — restored by the epilogue.)
    {
        // Weight preload under the scan's shadow:
        if (isLayer) {
            for (int i = tid; i < DIM * DIM; i += TPB) {
                sm.m.M[i] = __ldg(&msgW[i]);        // layer 0
                sm.m.G[i] = __ldg(&gateW[i]);
            }
        } else {
            for (int i = tid; i < 2 * DIM * 32; i += TPB) {
                int k = i >> 5, j = i & 31;
                sm.s.w[i] = make_float2(__ldg(&sW1[k * DIM + j]), __ldg(&sW1[k * DIM + j + 32]));
            }
        }

        // Seed the BS source nodes (block 0; published by bar0)
        if (bid == 0) {
            if (wl < BS) {
                int n = __ldg(&source[wl]);
                int r = __ldg(&qrel[wl]);
                if (lane == 0) {
                    g_slotmap[wl * NE + n] = wl + 1;
                    atomicOr(&g_mask[n], 1u << wl);
                    g_nlist[wl] = (n << 2) | wl;
                }
                g_h[wl * DIM + lane]      = __ldg(&ent[n * DIM + lane])      + __ldg(&qemb[r * DIM + lane]);
                g_h[wl * DIM + lane + 32] = __ldg(&ent[n * DIM + lane + 32]) + __ldg(&qemb[r * DIM + lane + 32]);
                g_agg[wl * DIM + lane] = 0.f;
                g_agg[wl * DIM + lane + 32] = 0.f;
            }
            if (tid == 0) { g_cnt[0] = BS; g_cnt[1] = BS; }
        }

        // Scan layer-0: compare against source ids in registers.
        int s0 = __ldg(&source[0]), s1 = __ldg(&source[1]);
        int s2 = __ldg(&source[2]), s3 = __ldg(&source[3]);
        const int CW = NEDGE / 4 / 32;
        for (int cw = gwarp; cw < CW; cw += gwarps) {
            int base = (cw * 32 + lane) * 4;
            int4 e4 = *reinterpret_cast<const int4*>(esrc + base);
            unsigned mm[4];
            mm[0] = (unsigned)(e4.x == s0) | ((unsigned)(e4.x == s1) << 1) |
                    ((unsigned)(e4.x == s2) << 2) | ((unsigned)(e4.x == s3) << 3);
            mm[1] = (unsigned)(e4.y == s0) | ((unsigned)(e4.y == s1) << 1) |
                    ((unsigned)(e4.y == s2) << 2) | ((unsigned)(e4.y == s3) << 3);
            mm[2] = (unsigned)(e4.z == s0) | ((unsigned)(e4.z == s1) << 1) |
                    ((unsigned)(e4.z == s2) << 2) | ((unsigned)(e4.z == s3) << 3);
            mm[3] = (unsigned)(e4.w == s0) | ((unsigned)(e4.w == s1) << 1) |
                    ((unsigned)(e4.w == s2) << 2) | ((unsigned)(e4.w == s3) << 3);
            push4(base, mm, 2, lane);
        }
    }
    bar_n(0, nb);

    // ---------------- bg-score blocks: dense score, then join -----------------
    if (!isLayer) {
        float rb0 = __ldg(&sb1[lane]), rb1 = __ldg(&sb1[lane + 32]);
        float rv0 = __ldg(&sW2[lane]), rv1 = __ldg(&sW2[lane + 32]);
        float b2 = __ldg(&sb2[0]);
        bg_score(sm, ent, out, rb0, rb1, rv0, rv1, b2, wl, lane,
                 (bid - nlb) * WPB + wl, pbg * WPB);
        bar_n(8, nb);           // join: bg writes globally visible
        return;                  // layer blocks finish the rest
    }

    // ========================= layer pipeline (nlb blocks) ====================
    for (int l = 0; l < NLAYERS; l++) {
        // ---- msg(l): claim target slots + matvec + atomic scatter ----
        {
            int total = __ldcg(&g_cnt[2 + l]);
            int pb = min(nlb, max(1, (total + WPB - 1) / WPB));
            if (bid < pb) {
                if (l > 0) {     // layer-0 weights preloaded in P0
                    for (int i = tid; i < DIM * DIM; i += TPB) {
                        sm.m.M[i] = __ldg(&msgW[l * DIM * DIM + i]);
                        sm.m.G[i] = __ldg(&gateW[l * DIM * DIM + i]);
                    }
                    __syncthreads();
                }
                for (int idx = bid * WPB + wl; idx < total; idx += pb * WPB) {
                    int p = __ldcg(&g_elist[idx]);
                    int e = p >> 2, b = p & 3;
                    int s = __ldg(&esrc[e]), t = __ldg(&etgt[e]), r = __ldg(&erel[e]);
                    int ss = __ldcg(&g_slotmap[b * NE + s]) - 1;

                    int* sp = &g_slotmap[b * NE + t];
                    int cur;
                    if (lane == 0) cur = atomicCAS(sp, 0, -1);
                    cur = __shfl_sync(FULL, cur, 0);
                    int ts;
                    if (cur == 0) {
                        int slot;
                        if (lane == 0) slot = atomicAdd(&g_cnt[0], 1);
                        slot = __shfl_sync(FULL, slot, 0);
                        g_h[slot * DIM + lane] = 0.f;       g_h[slot * DIM + lane + 32] = 0.f;
                        g_agg[slot * DIM + lane] = 0.f;     g_agg[slot * DIM + lane + 32] = 0.f;
                        __syncwarp();
                        __threadfence();
                        if (lane == 0) {
                            int ni = atomicAdd(&g_cnt[1], 1);
                            g_nlist[ni] = (t << 2) | b;
                            atomicOr(&g_mask[t], 1u << b);
                            atomicExch(sp, slot + 1);
                        }
                        ts = slot;
                    } else if (cur > 0) {
                        ts = cur - 1;
                    } else {
                        if (lane == 0) { do { cur = atomicAdd(sp, 0); } while (cur <= 0); }
                        cur = __shfl_sync(FULL, cur, 0);
                        ts = cur - 1;
                    }

                    sm.m.sh[wl][lane]      = __ldcg(&g_h[ss * DIM + lane]);
                    sm.m.sh[wl][lane + 32] = __ldcg(&g_h[ss * DIM + lane + 32]);
                    __syncwarp();
                    float m0 = 0.f, m1 = 0.f, q0 = 0.f, q1 = 0.f;
                    #pragma unroll 8
                    for (int k = 0; k < DIM; k++) {
                        float hk = sm.m.sh[wl][k];
                        m0 = fmaf(hk, sm.m.M[k * DIM + lane],      m0);
                        m1 = fmaf(hk, sm.m.M[k * DIM + lane + 32], m1);
                        q0 = fmaf(hk, sm.m.G[k * DIM + lane],      q0);
                        q1 = fmaf(hk, sm.m.G[k * DIM + lane + 32], q1);
                    }
                    const float* rr = rele + (size_t)(l * NREL + r) * DIM;
                    float v0 = __ldg(&rr[lane])      * m0 * (1.f / (1.f + expf(-q0)));
                    float v1 = __ldg(&rr[lane + 32]) * m1 * (1.f / (1.f + expf(-q1)));
                    atomicAdd(&g_agg[ts * DIM + lane],      v0);
                    atomicAdd(&g_agg[ts * DIM + lane + 32], v1);
                    __syncwarp();
                }
            }
        }
        bar_n(2 + 2 * l, nlb);

        // ---- scan(l+1) (layer warps) ----
        if (l + 1 < NLAYERS) scan_layer(esrc, l + 1, lwarp, lwarps, lane);

        // ---- update(l): h = LN(h + relu([h,agg]@W + b)) over nlist ----
        {
            int total = __ldcg(&g_cnt[1]);
            int pb = min(nlb, max(1, (total + WPB - 1) / WPB));
            if (bid < pb) {
                for (int i = tid; i < 2 * DIM * DIM; i += TPB)
                    sm.u.W[i] = __ldg(&updW[l * 2 * DIM * DIM + i]);
                __syncthreads();
                float ub0 = __ldg(&updb[l * DIM + lane]), ub1 = __ldg(&updb[l * DIM + lane + 32]);
                float lg0 = __ldg(&lng[l * DIM + lane]),  lg1 = __ldg(&lng[l * DIM + lane + 32]);
                float lb0 = __ldg(&lnb[l * DIM + lane]),  lb1 = __ldg(&lnb[l * DIM + lane + 32]);
                for (int idx = bid * WPB + wl; idx < total; idx += pb * WPB) {
                    int p = __ldcg(&g_nlist[idx]);
                    int n = p >> 2, b = p & 3;
                    int slot = __ldcg(&g_slotmap[b * NE + n]) - 1;
                    float h0 = __ldcg(&g_h[slot * DIM + lane]);
                    float h1 = __ldcg(&g_h[slot * DIM + lane + 32]);
                    float a0 = __ldcg(&g_agg[slot * DIM + lane]);
                    float a1 = __ldcg(&g_agg[slot * DIM + lane + 32]);
                    sm.u.x[wl][lane] = h0;      sm.u.x[wl][lane + 32] = h1;
                    sm.u.x[wl][64 + lane] = a0; sm.u.x[wl][96 + lane] = a1;
                    __syncwarp();
                    float u0 = ub0, u1 = ub1;
                    #pragma unroll 8
                    for (int k = 0; k < 2 * DIM; k++) {
                        float xk = sm.u.x[wl][k];
                        u0 = fmaf(xk, sm.u.W[k * DIM + lane],      u0);
                        u1 = fmaf(xk, sm.u.W[k * DIM + lane + 32], u1);
                    }
                    u0 = fmaxf(u0, 0.f); u1 = fmaxf(u1, 0.f);
                    float x0 = h0 + u0, x1 = h1 + u1;
                    float sums = x0 + x1;
                    #pragma unroll
                    for (int o = 16; o > 0; o >>= 1) sums += __shfl_xor_sync(FULL, sums, o);
                    float mean = sums * (1.f / 64.f);
                    float d0 = x0 - mean, d1 = x1 - mean;
                    float v = d0 * d0 + d1 * d1;
                    #pragma unroll
                    for (int o = 16; o > 0; o >>= 1) v += __shfl_xor_sync(FULL, v, o);
                    float inv = rsqrtf(v * (1.f / 64.f) + 1e-5f);
                    g_h[slot * DIM + lane]      = d0 * inv * lg0 + lb0;
                    g_h[slot * DIM + lane + 32] = d1 * inv * lg1 + lb1;
                    g_agg[slot * DIM + lane] = 0.f;
                    g_agg[slot * DIM + lane + 32] = 0.f;
                    __syncwarp();
                }
            }
        }
        bar_n(3 + 2 * l, nlb);
    }

    // ---------------- score weights + join + active overwrite pass ------------
    {
        for (int i = tid; i < 2 * DIM * 32; i += TPB) {
            int k = i >> 5, j = i & 31;
            sm.s.w[i] = make_float2(__ldg(&sW1[k * DIM + j]), __ldg(&sW1[k * DIM + j + 32]));
        }
        __syncthreads();
        float rb0 = __ldg(&sb1[lane]), rb1 = __ldg(&sb1[lane + 32]);
        float rv0 = __ldg(&sW2[lane]), rv1 = __ldg(&sW2[lane + 32]);
        float b2 = __ldg(&sb2[0]);

        bar_n(8, nb);     // join with bg blocks: all bg writes visible

        int nAct = __ldcg(&g_cnt[1]);
        float4* teA = sm.s.te4[wl][0];
        float* tep = reinterpret_cast<float*>(teA);
        for (int idx = lwarp; idx < nAct; idx += lwarps) {
            int p = __ldcg(&g_nlist[idx]);
            int n = p >> 2, b = p & 3;
            int slot = __ldcg(&g_slotmap[b * NE + n]) - 1;
            tep[lane]      = __ldcg(&g_h[slot * DIM + lane]);
            tep[lane + 32] = __ldcg(&g_h[slot * DIM + lane + 32]);
            tep[64 + lane] = __ldg(&ent[n * DIM + lane]);
            tep[96 + lane] = __ldg(&ent[n * DIM + lane + 32]);
            __syncwarp();
            float s0 = rb0, s1 = rb1;
            #pragma unroll 8
            for (int k = 0; k < 2 * DIM; k++) {
                float xk = tep[k];
                float2 wv = sm.s.w[k * 32 + lane];
                s0 = fmaf(xk, wv.x, s0);
                s1 = fmaf(xk, wv.y, s1);
            }
            float a = fmaxf(s0, 0.f) * rv0 + fmaxf(s1, 0.f) * rv1;
            #pragma unroll
            for (int o = 16; o > 0; o >>= 1) a += __shfl_xor_sync(FULL, a, o);
            if (lane == 0) out[b * NE + n] = a + b2;
            __syncwarp();
        }
    }

    // ---------------- pre-epilogue barrier (layer blocks) + cleanup -----------
    // Restores the all-zero invariant for the next launch/replay.
    __syncthreads();
    if (tid == 0) {
        __threadfence();
        atomicAdd(&g_bar[9], 1u);
    }
    if (bid == 0) {
        if (tid == 0) {
            while (*(volatile unsigned int*)&g_bar[9] < (unsigned)nlb) __nanosleep(128);
        }
        __syncthreads();
        int total = __ldcg(&g_cnt[1]);
        for (int i = tid; i < total; i += TPB) {
            int p = __ldcg(&g_nlist[i]);
            int n = p >> 2, b = p & 3;
            g_slotmap[b * NE + n] = 0;
            g_mask[n] = 0u;
        }
        __syncthreads();
        if (tid < 16) g_bar[tid] = 0u;
        if (tid < 8)  g_cnt[tid] = 0;
    }
}

extern "C" void kernel_launch(void* const* d_in, const int* in_sizes, int n_in,
                              void* d_out, int out_size) {
    const float* ent   = (const float*)d_in[0];
    const float* qemb  = (const float*)d_in[1];
    const float* rele  = (const float*)d_in[2];
    const float* msgW  = (const float*)d_in[3];
    const float* gateW = (const float*)d_in[4];
    const float* updW  = (const float*)d_in[5];
    const float* updb  = (const float*)d_in[6];
    const float* lng   = (const float*)d_in[7];
    const float* lnb   = (const float*)d_in[8];
    const float* sW1   = (const float*)d_in[9];
    const float* sb1   = (const float*)d_in[10];
    const float* sW2   = (const float*)d_in[11];
    const float* sb2   = (const float*)d_in[12];
    const int* source  = (const int*)d_in[13];
    const int* qrel    = (const int*)d_in[14];
    const int* esrc    = (const int*)d_in[15];
    const int* etgt    = (const int*)d_in[16];
    const int* erel    = (const int*)d_in[17];
    float* out = (float*)d_out;

    int dev = 0;
    cudaGetDevice(&dev);
    int sms = 0;
    cudaDeviceGetAttribute(&sms, cudaDevAttrMultiProcessorCount, dev);
    int maxb = 0;
    cudaOccupancyMaxActiveBlocksPerMultiprocessor(&maxb, k_all, TPB, 0);
    if (maxb < 1) maxb = 1;
    int grid = sms * maxb;

    k_all<<<grid, TPB>>>(ent, qemb, rele, msgW, gateW, updW, updb, lng, lnb,
                         sW1, sb1, sW2, sb2, source, qrel, esrc, etgt, erel, out);
}

// round 14
// speedup vs baseline: 1.4563x; 1.0542x over previous
#include <cuda_runtime.h>
#include <math.h>

#define NE      50000
#define DIM     64
#define NREL    400
#define NLAYERS 3
#define BS      4
#define NEDGE   400000
#define MAXSLOTS (BS * NE)
#define FULL 0xffffffffu
#define TPB 256
#define WPB (TPB / 32)

// ---------------- persistent device scratch (static, no allocation) ----------
// Invariant: slotmap/mask/cnt/bar are ALL-ZERO at kernel entry. Guaranteed by
// the loader on first launch and by the epilogue cleanup on every launch.
__device__ float        g_h[MAXSLOTS * DIM];
__device__ float        g_agg[MAXSLOTS * DIM];
__device__ float        g_actscore[MAXSLOTS];    // staged active scores
__device__ int          g_slotmap[BS * NE];      // slot+1, 0 = free, -1 = claiming
__device__ unsigned int g_mask[NE];              // bit b = (b,node) active
__device__ int          g_elist[BS * NEDGE];     // packed (edge<<2)|b
__device__ int          g_nlist[MAXSLOTS];       // packed (node<<2)|b
__device__ int          g_cnt[8];                // 0 slots, 1 nlist, 2+l edges/layer
__device__ unsigned int g_bar[16];               // barrier counters

struct SMemMsg { float M[DIM * DIM]; float G[DIM * DIM]; float sh[WPB][DIM]; };
struct SMemUpd { float W[2 * DIM * DIM]; float x[WPB][2 * DIM]; };
struct SMemSc  { float2 w[2 * DIM * 32]; float4 te4[WPB][2][DIM]; };
union SMemAll { SMemMsg m; SMemUpd u; SMemSc s; };

// Barrier over `count` blocks (arrivals strictly one per participating block).
__device__ __forceinline__ void bar_n(int i, unsigned count) {
    __syncthreads();
    if (threadIdx.x == 0) {
        __threadfence();
        atomicAdd(&g_bar[i], 1u);
        while (*(volatile unsigned int*)&g_bar[i] < count) __nanosleep(128);
    }
    __syncthreads();
}

// Warp-aggregated append of active (edge,batch) pairs into g_elist.
// Caller guarantees at least one lane has a nonzero mask (ballot pre-check).
__device__ __forceinline__ void push4(int base, const unsigned mm[4], int cslot, int lane) {
    int cnt = __popc(mm[0]) + __popc(mm[1]) + __popc(mm[2]) + __popc(mm[3]);
    int x = cnt;
    #pragma unroll
    for (int o = 1; o < 32; o <<= 1) {
        int y = __shfl_up_sync(FULL, x, o);
        if (lane >= o) x += y;
    }
    int warpTotal = __shfl_sync(FULL, x, 31);
    int basePos = 0;
    if (lane == 31) basePos = atomicAdd(&g_cnt[cslot], warpTotal);
    basePos = __shfl_sync(FULL, basePos, 31);
    int pos = basePos + x - cnt;
    #pragma unroll
    for (int j = 0; j < 4; j++) {
        unsigned m = mm[j];
        while (m) {
            int b = __ffs((int)m) - 1;
            m &= m - 1;
            g_elist[pos++] = ((base + j) << 2) | b;
        }
    }
}

__device__ __forceinline__ void scan_layer(const int* __restrict__ esrc, int layer,
                                           int gwarp, int gwarps, int lane) {
    const int CW = NEDGE / 4 / 32;   // 3125
    for (int cw = gwarp; cw < CW; cw += gwarps) {
        int base = (cw * 32 + lane) * 4;
        int4 e4 = *reinterpret_cast<const int4*>(esrc + base);
        unsigned mm[4];
        mm[0] = __ldcg(&g_mask[e4.x]);
        mm[1] = __ldcg(&g_mask[e4.y]);
        mm[2] = __ldcg(&g_mask[e4.z]);
        mm[3] = __ldcg(&g_mask[e4.w]);
        // fast path: whole warp empty -> skip prefix scan entirely
        if (__ballot_sync(FULL, (mm[0] | mm[1] | mm[2] | mm[3]) != 0u) == 0u) continue;
        push4(base, mm, 2 + layer, lane);
    }
}

// Background score for 8 nodes per item, written unconditionally to all batches.
__device__ __forceinline__ void bg_score(SMemAll& sm, const float* __restrict__ ent,
                                         float* __restrict__ out,
                                         float rb0, float rb1, float rv0, float rv1,
                                         float b2, int wl, int lane,
                                         int warp0, int warps) {
    const int nBg = NE / 8;   // 6250
    float4* teA = sm.s.te4[wl][0];
    float4* teB = sm.s.te4[wl][1];
    for (int w = warp0; w < nBg; w += warps) {
        int n0 = w * 8;
        float v0 = __ldg(&ent[(n0 + 0) * DIM + lane]);
        float v1 = __ldg(&ent[(n0 + 1) * DIM + lane]);
        float v2 = __ldg(&ent[(n0 + 2) * DIM + lane]);
        float v3 = __ldg(&ent[(n0 + 3) * DIM + lane]);
        float v4 = __ldg(&ent[(n0 + 4) * DIM + lane]);
        float v5 = __ldg(&ent[(n0 + 5) * DIM + lane]);
        float v6 = __ldg(&ent[(n0 + 6) * DIM + lane]);
        float v7 = __ldg(&ent[(n0 + 7) * DIM + lane]);
        float u0 = __ldg(&ent[(n0 + 0) * DIM + lane + 32]);
        float u1 = __ldg(&ent[(n0 + 1) * DIM + lane + 32]);
        float u2 = __ldg(&ent[(n0 + 2) * DIM + lane + 32]);
        float u3 = __ldg(&ent[(n0 + 3) * DIM + lane + 32]);
        float u4 = __ldg(&ent[(n0 + 4) * DIM + lane + 32]);
        float u5 = __ldg(&ent[(n0 + 5) * DIM + lane + 32]);
        float u6 = __ldg(&ent[(n0 + 6) * DIM + lane + 32]);
        float u7 = __ldg(&ent[(n0 + 7) * DIM + lane + 32]);
        teA[lane]      = make_float4(v0, v1, v2, v3);
        teA[lane + 32] = make_float4(u0, u1, u2, u3);
        teB[lane]      = make_float4(v4, v5, v6, v7);
        teB[lane + 32] = make_float4(u4, u5, u6, u7);
        __syncwarp();
        float s0[8], s1[8];
        #pragma unroll
        for (int j = 0; j < 8; j++) { s0[j] = rb0; s1[j] = rb1; }
        #pragma unroll 4
        for (int k = 0; k < DIM; k++) {
            float2 wv = sm.s.w[(DIM + k) * 32 + lane];
            float4 a = teA[k];
            float4 b = teB[k];
            s0[0] = fmaf(a.x, wv.x, s0[0]); s1[0] = fmaf(a.x, wv.y, s1[0]);
            s0[1] = fmaf(a.y, wv.x, s0[1]); s1[1] = fmaf(a.y, wv.y, s1[1]);
            s0[2] = fmaf(a.z, wv.x, s0[2]); s1[2] = fmaf(a.z, wv.y, s1[2]);
            s0[3] = fmaf(a.w, wv.x, s0[3]); s1[3] = fmaf(a.w, wv.y, s1[3]);
            s0[4] = fmaf(b.x, wv.x, s0[4]); s1[4] = fmaf(b.x, wv.y, s1[4]);
            s0[5] = fmaf(b.y, wv.x, s0[5]); s1[5] = fmaf(b.y, wv.y, s1[5]);
            s0[6] = fmaf(b.z, wv.x, s0[6]); s1[6] = fmaf(b.z, wv.y, s1[6]);
            s0[7] = fmaf(b.w, wv.x, s0[7]); s1[7] = fmaf(b.w, wv.y, s1[7]);
        }
        float sc[8];
        #pragma unroll
        for (int j = 0; j < 8; j++) {
            float a = fmaxf(s0[j], 0.f) * rv0 + fmaxf(s1[j], 0.f) * rv1;
            #pragma unroll
            for (int o = 16; o > 0; o >>= 1) a += __shfl_xor_sync(FULL, a, o);
            sc[j] = a + b2;
        }
        if (lane == 0) {
            float4 va = make_float4(sc[0], sc[1], sc[2], sc[3]);
            float4 vb = make_float4(sc[4], sc[5], sc[6], sc[7]);
            #pragma unroll
            for (int b = 0; b < BS; b++) {
                *reinterpret_cast<float4*>(&out[b * NE + n0])     = va;
                *reinterpret_cast<float4*>(&out[b * NE + n0 + 4]) = vb;
            }
        }
        __syncwarp();
    }
}

__global__ void __launch_bounds__(TPB, 2)
k_all(const float* __restrict__ ent, const float* __restrict__ qemb,
      const float* __restrict__ rele, const float* __restrict__ msgW,
      const float* __restrict__ gateW, const float* __restrict__ updW,
      const float* __restrict__ updb, const float* __restrict__ lng,
      const float* __restrict__ lnb, const float* __restrict__ sW1,
      const float* __restrict__ sb1, const float* __restrict__ sW2,
      const float* __restrict__ sb2, const int* __restrict__ source,
      const int* __restrict__ qrel, const int* __restrict__ esrc,
      const int* __restrict__ etgt, const int* __restrict__ erel,
      float* __restrict__ out) {
    __shared__ SMemAll sm;
    const int tid  = threadIdx.x;
    const int lane = tid & 31;
    const int wl   = tid >> 5;
    const int bid  = blockIdx.x;
    const int nb   = gridDim.x;
    const int pbg  = nb / 3;                // bg-score blocks
    const int nlb  = nb - pbg;              // layer-pipeline blocks
    const bool isLayer = bid < nlb;
    const int gthreads = nb * TPB;
    const int gwarps   = gthreads >> 5;
    const int gwarp    = bid * WPB + wl;
    const int gt       = bid * TPB + tid;
    const int lwarps   = nlb * WPB;
    const int lwarp    = gwarp;             // valid for layer blocks only

    // ---------------- P0: scan layer-0 + seed + weight preload ----------------
    {
        if (isLayer) {
            for (int i = tid; i < DIM * DIM; i += TPB) {
                sm.m.M[i] = __ldg(&msgW[i]);        // layer 0
                sm.m.G[i] = __ldg(&gateW[i]);
            }
        } else {
            for (int i = tid; i < 2 * DIM * 32; i += TPB) {
                int k = i >> 5, j = i & 31;
                sm.s.w[i] = make_float2(__ldg(&sW1[k * DIM + j]), __ldg(&sW1[k * DIM + j + 32]));
            }
        }

        if (bid == 0) {
            if (wl < BS) {
                int n = __ldg(&source[wl]);
                int r = __ldg(&qrel[wl]);
                if (lane == 0) {
                    g_slotmap[wl * NE + n] = wl + 1;
                    atomicOr(&g_mask[n], 1u << wl);
                    g_nlist[wl] = (n << 2) | wl;
                }
                g_h[wl * DIM + lane]      = __ldg(&ent[n * DIM + lane])      + __ldg(&qemb[r * DIM + lane]);
                g_h[wl * DIM + lane + 32] = __ldg(&ent[n * DIM + lane + 32]) + __ldg(&qemb[r * DIM + lane + 32]);
                g_agg[wl * DIM + lane] = 0.f;
                g_agg[wl * DIM + lane + 32] = 0.f;
            }
            if (tid == 0) { g_cnt[0] = BS; g_cnt[1] = BS; }
        }

        int s0 = __ldg(&source[0]), s1 = __ldg(&source[1]);
        int s2 = __ldg(&source[2]), s3 = __ldg(&source[3]);
        const int CW = NEDGE / 4 / 32;
        for (int cw = gwarp; cw < CW; cw += gwarps) {
            int base = (cw * 32 + lane) * 4;
            int4 e4 = *reinterpret_cast<const int4*>(esrc + base);
            unsigned mm[4];
            mm[0] = (unsigned)(e4.x == s0) | ((unsigned)(e4.x == s1) << 1) |
                    ((unsigned)(e4.x == s2) << 2) | ((unsigned)(e4.x == s3) << 3);
            mm[1] = (unsigned)(e4.y == s0) | ((unsigned)(e4.y == s1) << 1) |
                    ((unsigned)(e4.y == s2) << 2) | ((unsigned)(e4.y == s3) << 3);
            mm[2] = (unsigned)(e4.z == s0) | ((unsigned)(e4.z == s1) << 1) |
                    ((unsigned)(e4.z == s2) << 2) | ((unsigned)(e4.z == s3) << 3);
            mm[3] = (unsigned)(e4.w == s0) | ((unsigned)(e4.w == s1) << 1) |
                    ((unsigned)(e4.w == s2) << 2) | ((unsigned)(e4.w == s3) << 3);
            if (__ballot_sync(FULL, (mm[0] | mm[1] | mm[2] | mm[3]) != 0u) == 0u) continue;
            push4(base, mm, 2, lane);
        }
    }
    bar_n(0, nb);

    // ---------------- bg-score blocks ------------------------------------------
    if (!isLayer) {
        float rb0 = __ldg(&sb1[lane]), rb1 = __ldg(&sb1[lane + 32]);
        float rv0 = __ldg(&sW2[lane]), rv1 = __ldg(&sW2[lane + 32]);
        float b2 = __ldg(&sb2[0]);
        bg_score(sm, ent, out, rb0, rb1, rv0, rv1, b2, wl, lane,
                 (bid - nlb) * WPB + wl, pbg * WPB);
        bar_n(8, nb);           // join: bg + actscore writes globally visible
        // scatter staged active scores (shared with layer blocks)
        int nAct = __ldcg(&g_cnt[1]);
        for (int i = gt; i < nAct; i += gthreads) {
            int p = __ldcg(&g_nlist[i]);
            out[(p & 3) * NE + (p >> 2)] = __ldcg(&g_actscore[i]);
        }
        // final arrive-only barrier
        __syncthreads();
        if (tid == 0) { __threadfence(); atomicAdd(&g_bar[9], 1u); }
        return;
    }

    // ========================= layer pipeline (nlb blocks) ====================
    for (int l = 0; l < NLAYERS; l++) {
        // ---- msg(l) ----
        {
            int total = __ldcg(&g_cnt[2 + l]);
            int pb = min(nlb, max(1, (total + WPB - 1) / WPB));
            if (bid < pb) {
                if (l > 0) {     // layer-0 weights preloaded in P0
                    for (int i = tid; i < DIM * DIM; i += TPB) {
                        sm.m.M[i] = __ldg(&msgW[l * DIM * DIM + i]);
                        sm.m.G[i] = __ldg(&gateW[l * DIM * DIM + i]);
                    }
                    __syncthreads();
                }
                for (int idx = bid * WPB + wl; idx < total; idx += pb * WPB) {
                    int p = __ldcg(&g_elist[idx]);
                    int e = p >> 2, b = p & 3;
                    int s = __ldg(&esrc[e]), t = __ldg(&etgt[e]), r = __ldg(&erel[e]);
                    int ss = __ldcg(&g_slotmap[b * NE + s]) - 1;

                    int* sp = &g_slotmap[b * NE + t];
                    int cur;
                    if (lane == 0) cur = atomicCAS(sp, 0, -1);
                    cur = __shfl_sync(FULL, cur, 0);
                    int ts;
                    if (cur == 0) {
                        int slot;
                        if (lane == 0) slot = atomicAdd(&g_cnt[0], 1);
                        slot = __shfl_sync(FULL, slot, 0);
                        g_h[slot * DIM + lane] = 0.f;       g_h[slot * DIM + lane + 32] = 0.f;
                        g_agg[slot * DIM + lane] = 0.f;     g_agg[slot * DIM + lane + 32] = 0.f;
                        __syncwarp();
                        __threadfence();
                        if (lane == 0) {
                            int ni = atomicAdd(&g_cnt[1], 1);
                            g_nlist[ni] = (t << 2) | b;
                            atomicOr(&g_mask[t], 1u << b);
                            atomicExch(sp, slot + 1);
                        }
                        ts = slot;
                    } else if (cur > 0) {
                        ts = cur - 1;
                    } else {
                        if (lane == 0) { do { cur = atomicAdd(sp, 0); } while (cur <= 0); }
                        cur = __shfl_sync(FULL, cur, 0);
                        ts = cur - 1;
                    }

                    sm.m.sh[wl][lane]      = __ldcg(&g_h[ss * DIM + lane]);
                    sm.m.sh[wl][lane + 32] = __ldcg(&g_h[ss * DIM + lane + 32]);
                    __syncwarp();
                    float m0 = 0.f, m1 = 0.f, q0 = 0.f, q1 = 0.f;
                    #pragma unroll 8
                    for (int k = 0; k < DIM; k++) {
                        float hk = sm.m.sh[wl][k];
                        m0 = fmaf(hk, sm.m.M[k * DIM + lane],      m0);
                        m1 = fmaf(hk, sm.m.M[k * DIM + lane + 32], m1);
                        q0 = fmaf(hk, sm.m.G[k * DIM + lane],      q0);
                        q1 = fmaf(hk, sm.m.G[k * DIM + lane + 32], q1);
                    }
                    const float* rr = rele + (size_t)(l * NREL + r) * DIM;
                    float v0 = __ldg(&rr[lane])      * m0 * (1.f / (1.f + expf(-q0)));
                    float v1 = __ldg(&rr[lane + 32]) * m1 * (1.f / (1.f + expf(-q1)));
                    atomicAdd(&g_agg[ts * DIM + lane],      v0);
                    atomicAdd(&g_agg[ts * DIM + lane + 32], v1);
                    __syncwarp();
                }
            }
        }
        bar_n(2 + 2 * l, nlb);

        // ---- scan(l+1) (layer warps) ----
        if (l + 1 < NLAYERS) scan_layer(esrc, l + 1, lwarp, lwarps, lane);

        // ---- update(l) ----
        {
            int total = __ldcg(&g_cnt[1]);
            int pb = min(nlb, max(1, (total + WPB - 1) / WPB));
            if (bid < pb) {
                for (int i = tid; i < 2 * DIM * DIM; i += TPB)
                    sm.u.W[i] = __ldg(&updW[l * 2 * DIM * DIM + i]);
                __syncthreads();
                float ub0 = __ldg(&updb[l * DIM + lane]), ub1 = __ldg(&updb[l * DIM + lane + 32]);
                float lg0 = __ldg(&lng[l * DIM + lane]),  lg1 = __ldg(&lng[l * DIM + lane + 32]);
                float lb0 = __ldg(&lnb[l * DIM + lane]),  lb1 = __ldg(&lnb[l * DIM + lane + 32]);
                for (int idx = bid * WPB + wl; idx < total; idx += pb * WPB) {
                    int p = __ldcg(&g_nlist[idx]);
                    int n = p >> 2, b = p & 3;
                    int slot = __ldcg(&g_slotmap[b * NE + n]) - 1;
                    float h0 = __ldcg(&g_h[slot * DIM + lane]);
                    float h1 = __ldcg(&g_h[slot * DIM + lane + 32]);
                    float a0 = __ldcg(&g_agg[slot * DIM + lane]);
                    float a1 = __ldcg(&g_agg[slot * DIM + lane + 32]);
                    sm.u.x[wl][lane] = h0;      sm.u.x[wl][lane + 32] = h1;
                    sm.u.x[wl][64 + lane] = a0; sm.u.x[wl][96 + lane] = a1;
                    __syncwarp();
                    float u0 = ub0, u1 = ub1;
                    #pragma unroll 8
                    for (int k = 0; k < 2 * DIM; k++) {
                        float xk = sm.u.x[wl][k];
                        u0 = fmaf(xk, sm.u.W[k * DIM + lane],      u0);
                        u1 = fmaf(xk, sm.u.W[k * DIM + lane + 32], u1);
                    }
                    u0 = fmaxf(u0, 0.f); u1 = fmaxf(u1, 0.f);
                    float x0 = h0 + u0, x1 = h1 + u1;
                    float sums = x0 + x1;
                    #pragma unroll
                    for (int o = 16; o > 0; o >>= 1) sums += __shfl_xor_sync(FULL, sums, o);
                    float mean = sums * (1.f / 64.f);
                    float d0 = x0 - mean, d1 = x1 - mean;
                    float v = d0 * d0 + d1 * d1;
                    #pragma unroll
                    for (int o = 16; o > 0; o >>= 1) v += __shfl_xor_sync(FULL, v, o);
                    float inv = rsqrtf(v * (1.f / 64.f) + 1e-5f);
                    g_h[slot * DIM + lane]      = d0 * inv * lg0 + lb0;
                    g_h[slot * DIM + lane + 32] = d1 * inv * lg1 + lb1;
                    g_agg[slot * DIM + lane] = 0.f;
                    g_agg[slot * DIM + lane + 32] = 0.f;
                    __syncwarp();
                }
            }
        }
        bar_n(3 + 2 * l, nlb);
    }

    // ---------------- active scores -> scratch, join, scatter -----------------
    {
        for (int i = tid; i < 2 * DIM * 32; i += TPB) {
            int k = i >> 5, j = i & 31;
            sm.s.w[i] = make_float2(__ldg(&sW1[k * DIM + j]), __ldg(&sW1[k * DIM + j + 32]));
        }
        __syncthreads();
        float rb0 = __ldg(&sb1[lane]), rb1 = __ldg(&sb1[lane + 32]);
        float rv0 = __ldg(&sW2[lane]), rv1 = __ldg(&sW2[lane + 32]);
        float b2 = __ldg(&sb2[0]);

        int nAct = __ldcg(&g_cnt[1]);
        float4* teA = sm.s.te4[wl][0];
        float* tep = reinterpret_cast<float*>(teA);
        for (int idx = lwarp; idx < nAct; idx += lwarps) {
            int p = __ldcg(&g_nlist[idx]);
            int n = p >> 2, b = p & 3;
            int slot = __ldcg(&g_slotmap[b * NE + n]) - 1;
            tep[lane]      = __ldcg(&g_h[slot * DIM + lane]);
            tep[lane + 32] = __ldcg(&g_h[slot * DIM + lane + 32]);
            tep[64 + lane] = __ldg(&ent[n * DIM + lane]);
            tep[96 + lane] = __ldg(&ent[n * DIM + lane + 32]);
            __syncwarp();
            float s0 = rb0, s1 = rb1;
            #pragma unroll 8
            for (int k = 0; k < 2 * DIM; k++) {
                float xk = tep[k];
                float2 wv = sm.s.w[k * 32 + lane];
                s0 = fmaf(xk, wv.x, s0);
                s1 = fmaf(xk, wv.y, s1);
            }
            float a = fmaxf(s0, 0.f) * rv0 + fmaxf(s1, 0.f) * rv1;
            #pragma unroll
            for (int o = 16; o > 0; o >>= 1) a += __shfl_xor_sync(FULL, a, o);
            if (lane == 0) g_actscore[idx] = a + b2;   // staged, not out
            __syncwarp();
        }

        bar_n(8, nb);     // join: bg writes + staged scores visible everywhere

        // scatter staged scores (all blocks participate)
        for (int i = gt; i < nAct; i += gthreads) {
            int p = __ldcg(&g_nlist[i]);
            out[(p & 3) * NE + (p >> 2)] = __ldcg(&g_actscore[i]);
        }
    }

    // ---------------- final barrier (ALL blocks) + cleanup (block 0) ----------
    // bar9 counts nb: no block can still be polling bar8 when block 0 resets.
    __syncthreads();
    if (tid == 0) {
        __threadfence();
        atomicAdd(&g_bar[9], 1u);
    }
    if (bid == 0) {
        if (tid == 0) {
            while (*(volatile unsigned int*)&g_bar[9] < (unsigned)nb) __nanosleep(128);
        }
        __syncthreads();
        int total = __ldcg(&g_cnt[1]);
        for (int i = tid; i < total; i += TPB) {
            int p = __ldcg(&g_nlist[i]);
            int n = p >> 2, b = p & 3;
            g_slotmap[b * NE + n] = 0;
            g_mask[n] = 0u;
        }
        __syncthreads();
        if (tid < 16) g_bar[tid] = 0u;
        if (tid < 8)  g_cnt[tid] = 0;
    }
}

extern "C" void kernel_launch(void* const* d_in, const int* in_sizes, int n_in,
                              void* d_out, int out_size) {
    const float* ent   = (const float*)d_in[0];
    const float* qemb  = (const float*)d_in[1];
    const float* rele  = (const float*)d_in[2];
    const float* msgW  = (const float*)d_in[3];
    const float* gateW = (const float*)d_in[4];
    const float* updW  = (const float*)d_in[5];
    const float* updb  = (const float*)d_in[6];
    const float* lng   = (const float*)d_in[7];
    const float* lnb   = (const float*)d_in[8];
    const float* sW1   = (const float*)d_in[9];
    const float* sb1   = (const float*)d_in[10];
    const float* sW2   = (const float*)d_in[11];
    const float* sb2   = (const float*)d_in[12];
    const int* source  = (const int*)d_in[13];
    const int* qrel    = (const int*)d_in[14];
    const int* esrc    = (const int*)d_in[15];
    const int* etgt    = (const int*)d_in[16];
    const int* erel    = (const int*)d_in[17];
    float* out = (float*)d_out;

    int dev = 0;
    cudaGetDevice(&dev);
    int sms = 0;
    cudaDeviceGetAttribute(&sms, cudaDevAttrMultiProcessorCount, dev);
    int maxb = 0;
    cudaOccupancyMaxActiveBlocksPerMultiprocessor(&maxb, k_all, TPB, 0);
    if (maxb < 1) maxb = 1;
    int grid = sms * maxb;

    k_all<<<grid, TPB>>>(ent, qemb, rele, msgW, gateW, updW, updb, lng, lnb,
                         sW1, sb1, sW2, sb2, source, qrel, esrc, etgt, erel, out);
}

// round 15
// speedup vs baseline: 1.5154x; 1.0406x over previous
#include <cuda_runtime.h>
#include <math.h>

#define NE      50000
#define DIM     64
#define NREL    400
#define NLAYERS 3
#define BS      4
#define NEDGE   400000
#define MAXSLOTS (BS * NE)
#define FULL 0xffffffffu
#define TPB 256
#define WPB (TPB / 32)

// ---------------- persistent device scratch (static, no allocation) ----------
// Invariant: slotmap/mask/cnt/bar are ALL-ZERO at kernel entry. Guaranteed by
// the loader on first launch and by the epilogue cleanup on every launch.
__device__ float        g_h[MAXSLOTS * DIM];
__device__ float        g_agg[MAXSLOTS * DIM];
__device__ float        g_actscore[MAXSLOTS];    // staged active scores
__device__ int          g_slotmap[BS * NE];      // slot+1, 0 = free, -1 = claiming
__device__ unsigned int g_mask[NE];              // bit b = (b,node) active
__device__ int          g_elist[BS * NEDGE];     // packed (edge<<2)|b
__device__ int          g_nlist[MAXSLOTS];       // packed (node<<2)|b
__device__ int          g_cnt[8];                // 0 slots, 1 nlist, 2+l edges/layer
__device__ unsigned int g_bar[16];               // barrier counters

struct SMemMsg { float M[DIM * DIM]; float G[DIM * DIM]; float sh[WPB][DIM]; };
struct SMemUpd { float W[2 * DIM * DIM]; float x[WPB][2 * DIM]; };
struct SMemSc  { float2 w[2 * DIM * 32]; float4 te4[WPB][2][DIM]; };
union SMemAll { SMemMsg m; SMemUpd u; SMemSc s; };

// Barrier over `count` blocks (arrivals strictly one per participating block).
__device__ __forceinline__ void bar_n(int i, unsigned count) {
    __syncthreads();
    if (threadIdx.x == 0) {
        __threadfence();
        atomicAdd(&g_bar[i], 1u);
        while (*(volatile unsigned int*)&g_bar[i] < count) __nanosleep(64);
    }
    __syncthreads();
}

// Warp-aggregated append of active (edge,batch) pairs into g_elist.
// Caller guarantees at least one lane has a nonzero mask (ballot pre-check).
__device__ __forceinline__ void push4(int base, const unsigned mm[4], int cslot, int lane) {
    int cnt = __popc(mm[0]) + __popc(mm[1]) + __popc(mm[2]) + __popc(mm[3]);
    int x = cnt;
    #pragma unroll
    for (int o = 1; o < 32; o <<= 1) {
        int y = __shfl_up_sync(FULL, x, o);
        if (lane >= o) x += y;
    }
    int warpTotal = __shfl_sync(FULL, x, 31);
    int basePos = 0;
    if (lane == 31) basePos = atomicAdd(&g_cnt[cslot], warpTotal);
    basePos = __shfl_sync(FULL, basePos, 31);
    int pos = basePos + x - cnt;
    #pragma unroll
    for (int j = 0; j < 4; j++) {
        unsigned m = mm[j];
        while (m) {
            int b = __ffs((int)m) - 1;
            m &= m - 1;
            g_elist[pos++] = ((base + j) << 2) | b;
        }
    }
}

__device__ __forceinline__ void scan_layer(const int* __restrict__ esrc, int layer,
                                           int gwarp, int gwarps, int lane) {
    const int CW = NEDGE / 4 / 32;   // 3125
    for (int cw = gwarp; cw < CW; cw += gwarps) {
        int base = (cw * 32 + lane) * 4;
        int4 e4 = *reinterpret_cast<const int4*>(esrc + base);
        unsigned mm[4];
        mm[0] = __ldcg(&g_mask[e4.x]);
        mm[1] = __ldcg(&g_mask[e4.y]);
        mm[2] = __ldcg(&g_mask[e4.z]);
        mm[3] = __ldcg(&g_mask[e4.w]);
        // fast path: whole warp empty -> skip prefix scan entirely
        if (__ballot_sync(FULL, (mm[0] | mm[1] | mm[2] | mm[3]) != 0u) == 0u) continue;
        push4(base, mm, 2 + layer, lane);
    }
}

// Background score for 8 nodes per item, written unconditionally to all batches.
__device__ __forceinline__ void bg_score(SMemAll& sm, const float* __restrict__ ent,
                                         float* __restrict__ out,
                                         float rb0, float rb1, float rv0, float rv1,
                                         float b2, int wl, int lane,
                                         int warp0, int warps) {
    const int nBg = NE / 8;   // 6250
    float4* teA = sm.s.te4[wl][0];
    float4* teB = sm.s.te4[wl][1];
    for (int w = warp0; w < nBg; w += warps) {
        int n0 = w * 8;
        float v0 = __ldg(&ent[(n0 + 0) * DIM + lane]);
        float v1 = __ldg(&ent[(n0 + 1) * DIM + lane]);
        float v2 = __ldg(&ent[(n0 + 2) * DIM + lane]);
        float v3 = __ldg(&ent[(n0 + 3) * DIM + lane]);
        float v4 = __ldg(&ent[(n0 + 4) * DIM + lane]);
        float v5 = __ldg(&ent[(n0 + 5) * DIM + lane]);
        float v6 = __ldg(&ent[(n0 + 6) * DIM + lane]);
        float v7 = __ldg(&ent[(n0 + 7) * DIM + lane]);
        float u0 = __ldg(&ent[(n0 + 0) * DIM + lane + 32]);
        float u1 = __ldg(&ent[(n0 + 1) * DIM + lane + 32]);
        float u2 = __ldg(&ent[(n0 + 2) * DIM + lane + 32]);
        float u3 = __ldg(&ent[(n0 + 3) * DIM + lane + 32]);
        float u4 = __ldg(&ent[(n0 + 4) * DIM + lane + 32]);
        float u5 = __ldg(&ent[(n0 + 5) * DIM + lane + 32]);
        float u6 = __ldg(&ent[(n0 + 6) * DIM + lane + 32]);
        float u7 = __ldg(&ent[(n0 + 7) * DIM + lane + 32]);
        teA[lane]      = make_float4(v0, v1, v2, v3);
        teA[lane + 32] = make_float4(u0, u1, u2, u3);
        teB[lane]      = make_float4(v4, v5, v6, v7);
        teB[lane + 32] = make_float4(u4, u5, u6, u7);
        __syncwarp();
        float s0[8], s1[8];
        #pragma unroll
        for (int j = 0; j < 8; j++) { s0[j] = rb0; s1[j] = rb1; }
        #pragma unroll 4
        for (int k = 0; k < DIM; k++) {
            float2 wv = sm.s.w[(DIM + k) * 32 + lane];
            float4 a = teA[k];
            float4 b = teB[k];
            s0[0] = fmaf(a.x, wv.x, s0[0]); s1[0] = fmaf(a.x, wv.y, s1[0]);
            s0[1] = fmaf(a.y, wv.x, s0[1]); s1[1] = fmaf(a.y, wv.y, s1[1]);
            s0[2] = fmaf(a.z, wv.x, s0[2]); s1[2] = fmaf(a.z, wv.y, s1[2]);
            s0[3] = fmaf(a.w, wv.x, s0[3]); s1[3] = fmaf(a.w, wv.y, s1[3]);
            s0[4] = fmaf(b.x, wv.x, s0[4]); s1[4] = fmaf(b.x, wv.y, s1[4]);
            s0[5] = fmaf(b.y, wv.x, s0[5]); s1[5] = fmaf(b.y, wv.y, s1[5]);
            s0[6] = fmaf(b.z, wv.x, s0[6]); s1[6] = fmaf(b.z, wv.y, s1[6]);
            s0[7] = fmaf(b.w, wv.x, s0[7]); s1[7] = fmaf(b.w, wv.y, s1[7]);
        }
        float sc[8];
        #pragma unroll
        for (int j = 0; j < 8; j++) {
            float a = fmaxf(s0[j], 0.f) * rv0 + fmaxf(s1[j], 0.f) * rv1;
            #pragma unroll
            for (int o = 16; o > 0; o >>= 1) a += __shfl_xor_sync(FULL, a, o);
            sc[j] = a + b2;
        }
        if (lane == 0) {
            float4 va = make_float4(sc[0], sc[1], sc[2], sc[3]);
            float4 vb = make_float4(sc[4], sc[5], sc[6], sc[7]);
            #pragma unroll
            for (int b = 0; b < BS; b++) {
                *reinterpret_cast<float4*>(&out[b * NE + n0])     = va;
                *reinterpret_cast<float4*>(&out[b * NE + n0 + 4]) = vb;
            }
        }
        __syncwarp();
    }
}

// Post-join: scatter staged active scores AND restore the zero invariant for
// the entries this thread touches (disjoint arrays; both safe after bar8).
__device__ __forceinline__ void scatter_and_clean(float* __restrict__ out,
                                                  int nAct, int gt, int gthreads) {
    for (int i = gt; i < nAct; i += gthreads) {
        int p = __ldcg(&g_nlist[i]);
        int n = p >> 2, b = p & 3;
        out[b * NE + n] = __ldcg(&g_actscore[i]);
        g_slotmap[b * NE + n] = 0;
        g_mask[n] = 0u;           // duplicate writes across b are benign
    }
}

__global__ void __launch_bounds__(TPB, 2)
k_all(const float* __restrict__ ent, const float* __restrict__ qemb,
      const float* __restrict__ rele, const float* __restrict__ msgW,
      const float* __restrict__ gateW, const float* __restrict__ updW,
      const float* __restrict__ updb, const float* __restrict__ lng,
      const float* __restrict__ lnb, const float* __restrict__ sW1,
      const float* __restrict__ sb1, const float* __restrict__ sW2,
      const float* __restrict__ sb2, const int* __restrict__ source,
      const int* __restrict__ qrel, const int* __restrict__ esrc,
      const int* __restrict__ etgt, const int* __restrict__ erel,
      float* __restrict__ out) {
    __shared__ SMemAll sm;
    const int tid  = threadIdx.x;
    const int lane = tid & 31;
    const int wl   = tid >> 5;
    const int bid  = blockIdx.x;
    const int nb   = gridDim.x;
    const int pbg  = nb / 3;                // bg-score blocks
    const int nlb  = nb - pbg;              // layer-pipeline blocks
    const bool isLayer = bid < nlb;
    const int gthreads = nb * TPB;
    const int gwarps   = gthreads >> 5;
    const int gwarp    = bid * WPB + wl;
    const int gt       = bid * TPB + tid;
    const int lwarps   = nlb * WPB;
    const int lwarp    = gwarp;             // valid for layer blocks only

    // ---------------- P0: scan layer-0 + seed + weight preload ----------------
    {
        if (isLayer) {
            for (int i = tid; i < DIM * DIM; i += TPB) {
                sm.m.M[i] = __ldg(&msgW[i]);        // layer 0
                sm.m.G[i] = __ldg(&gateW[i]);
            }
        } else {
            for (int i = tid; i < 2 * DIM * 32; i += TPB) {
                int k = i >> 5, j = i & 31;
                sm.s.w[i] = make_float2(__ldg(&sW1[k * DIM + j]), __ldg(&sW1[k * DIM + j + 32]));
            }
        }

        if (bid == 0) {
            if (wl < BS) {
                int n = __ldg(&source[wl]);
                int r = __ldg(&qrel[wl]);
                if (lane == 0) {
                    g_slotmap[wl * NE + n] = wl + 1;
                    atomicOr(&g_mask[n], 1u << wl);
                    g_nlist[wl] = (n << 2) | wl;
                }
                g_h[wl * DIM + lane]      = __ldg(&ent[n * DIM + lane])      + __ldg(&qemb[r * DIM + lane]);
                g_h[wl * DIM + lane + 32] = __ldg(&ent[n * DIM + lane + 32]) + __ldg(&qemb[r * DIM + lane + 32]);
                g_agg[wl * DIM + lane] = 0.f;
                g_agg[wl * DIM + lane + 32] = 0.f;
            }
            if (tid == 0) { g_cnt[0] = BS; g_cnt[1] = BS; }
        }

        int s0 = __ldg(&source[0]), s1 = __ldg(&source[1]);
        int s2 = __ldg(&source[2]), s3 = __ldg(&source[3]);
        const int CW = NEDGE / 4 / 32;
        for (int cw = gwarp; cw < CW; cw += gwarps) {
            int base = (cw * 32 + lane) * 4;
            int4 e4 = *reinterpret_cast<const int4*>(esrc + base);
            unsigned mm[4];
            mm[0] = (unsigned)(e4.x == s0) | ((unsigned)(e4.x == s1) << 1) |
                    ((unsigned)(e4.x == s2) << 2) | ((unsigned)(e4.x == s3) << 3);
            mm[1] = (unsigned)(e4.y == s0) | ((unsigned)(e4.y == s1) << 1) |
                    ((unsigned)(e4.y == s2) << 2) | ((unsigned)(e4.y == s3) << 3);
            mm[2] = (unsigned)(e4.z == s0) | ((unsigned)(e4.z == s1) << 1) |
                    ((unsigned)(e4.z == s2) << 2) | ((unsigned)(e4.z == s3) << 3);
            mm[3] = (unsigned)(e4.w == s0) | ((unsigned)(e4.w == s1) << 1) |
                    ((unsigned)(e4.w == s2) << 2) | ((unsigned)(e4.w == s3) << 3);
            if (__ballot_sync(FULL, (mm[0] | mm[1] | mm[2] | mm[3]) != 0u) == 0u) continue;
            push4(base, mm, 2, lane);
        }
    }
    bar_n(0, nb);

    // ---------------- bg-score blocks ------------------------------------------
    if (!isLayer) {
        float rb0 = __ldg(&sb1[lane]), rb1 = __ldg(&sb1[lane + 32]);
        float rv0 = __ldg(&sW2[lane]), rv1 = __ldg(&sW2[lane + 32]);
        float b2 = __ldg(&sb2[0]);
        bg_score(sm, ent, out, rb0, rb1, rv0, rv1, b2, wl, lane,
                 (bid - nlb) * WPB + wl, pbg * WPB);
        bar_n(8, nb);           // join: bg + actscore writes globally visible
        int nAct = __ldcg(&g_cnt[1]);
        scatter_and_clean(out, nAct, gt, gthreads);
        __syncthreads();
        if (tid == 0) { __threadfence(); atomicAdd(&g_bar[9], 1u); }
        return;
    }

    // ========================= layer pipeline (nlb blocks) ====================
    for (int l = 0; l < NLAYERS; l++) {
        // ---- msg(l) ----
        {
            int total = __ldcg(&g_cnt[2 + l]);
            int pb = min(nlb, max(1, (total + WPB - 1) / WPB));
            if (bid < pb) {
                if (l > 0) {     // layer-0 weights preloaded in P0
                    for (int i = tid; i < DIM * DIM; i += TPB) {
                        sm.m.M[i] = __ldg(&msgW[l * DIM * DIM + i]);
                        sm.m.G[i] = __ldg(&gateW[l * DIM * DIM + i]);
                    }
                    __syncthreads();
                }
                for (int idx = bid * WPB + wl; idx < total; idx += pb * WPB) {
                    int p = __ldcg(&g_elist[idx]);
                    int e = p >> 2, b = p & 3;
                    int s = __ldg(&esrc[e]), t = __ldg(&etgt[e]), r = __ldg(&erel[e]);
                    int ss = __ldcg(&g_slotmap[b * NE + s]) - 1;

                    int* sp = &g_slotmap[b * NE + t];
                    int cur;
                    if (lane == 0) cur = atomicCAS(sp, 0, -1);
                    cur = __shfl_sync(FULL, cur, 0);
                    int ts;
                    if (cur == 0) {
                        int slot;
                        if (lane == 0) slot = atomicAdd(&g_cnt[0], 1);
                        slot = __shfl_sync(FULL, slot, 0);
                        g_h[slot * DIM + lane] = 0.f;       g_h[slot * DIM + lane + 32] = 0.f;
                        g_agg[slot * DIM + lane] = 0.f;     g_agg[slot * DIM + lane + 32] = 0.f;
                        __syncwarp();
                        __threadfence();
                        if (lane == 0) {
                            int ni = atomicAdd(&g_cnt[1], 1);
                            g_nlist[ni] = (t << 2) | b;
                            atomicOr(&g_mask[t], 1u << b);
                            atomicExch(sp, slot + 1);
                        }
                        ts = slot;
                    } else if (cur > 0) {
                        ts = cur - 1;
                    } else {
                        if (lane == 0) { do { cur = atomicAdd(sp, 0); } while (cur <= 0); }
                        cur = __shfl_sync(FULL, cur, 0);
                        ts = cur - 1;
                    }

                    sm.m.sh[wl][lane]      = __ldcg(&g_h[ss * DIM + lane]);
                    sm.m.sh[wl][lane + 32] = __ldcg(&g_h[ss * DIM + lane + 32]);
                    __syncwarp();
                    float m0 = 0.f, m1 = 0.f, q0 = 0.f, q1 = 0.f;
                    #pragma unroll 8
                    for (int k = 0; k < DIM; k++) {
                        float hk = sm.m.sh[wl][k];
                        m0 = fmaf(hk, sm.m.M[k * DIM + lane],      m0);
                        m1 = fmaf(hk, sm.m.M[k * DIM + lane + 32], m1);
                        q0 = fmaf(hk, sm.m.G[k * DIM + lane],      q0);
                        q1 = fmaf(hk, sm.m.G[k * DIM + lane + 32], q1);
                    }
                    const float* rr = rele + (size_t)(l * NREL + r) * DIM;
                    float v0 = __ldg(&rr[lane])      * m0 * (1.f / (1.f + expf(-q0)));
                    float v1 = __ldg(&rr[lane + 32]) * m1 * (1.f / (1.f + expf(-q1)));
                    atomicAdd(&g_agg[ts * DIM + lane],      v0);
                    atomicAdd(&g_agg[ts * DIM + lane + 32], v1);
                    __syncwarp();
                }
            }
        }
        bar_n(2 + 2 * l, nlb);

        // ---- scan(l+1) (layer warps) ----
        if (l + 1 < NLAYERS) scan_layer(esrc, l + 1, lwarp, lwarps, lane);

        // ---- update(l) ----
        {
            int total = __ldcg(&g_cnt[1]);
            int pb = min(nlb, max(1, (total + WPB - 1) / WPB));
            if (bid < pb) {
                for (int i = tid; i < 2 * DIM * DIM; i += TPB)
                    sm.u.W[i] = __ldg(&updW[l * 2 * DIM * DIM + i]);
                __syncthreads();
                float ub0 = __ldg(&updb[l * DIM + lane]), ub1 = __ldg(&updb[l * DIM + lane + 32]);
                float lg0 = __ldg(&lng[l * DIM + lane]),  lg1 = __ldg(&lng[l * DIM + lane + 32]);
                float lb0 = __ldg(&lnb[l * DIM + lane]),  lb1 = __ldg(&lnb[l * DIM + lane + 32]);
                for (int idx = bid * WPB + wl; idx < total; idx += pb * WPB) {
                    int p = __ldcg(&g_nlist[idx]);
                    int n = p >> 2, b = p & 3;
                    int slot = __ldcg(&g_slotmap[b * NE + n]) - 1;
                    float h0 = __ldcg(&g_h[slot * DIM + lane]);
                    float h1 = __ldcg(&g_h[slot * DIM + lane + 32]);
                    float a0 = __ldcg(&g_agg[slot * DIM + lane]);
                    float a1 = __ldcg(&g_agg[slot * DIM + lane + 32]);
                    sm.u.x[wl][lane] = h0;      sm.u.x[wl][lane + 32] = h1;
                    sm.u.x[wl][64 + lane] = a0; sm.u.x[wl][96 + lane] = a1;
                    __syncwarp();
                    float u0 = ub0, u1 = ub1;
                    #pragma unroll 8
                    for (int k = 0; k < 2 * DIM; k++) {
                        float xk = sm.u.x[wl][k];
                        u0 = fmaf(xk, sm.u.W[k * DIM + lane],      u0);
                        u1 = fmaf(xk, sm.u.W[k * DIM + lane + 32], u1);
                    }
                    u0 = fmaxf(u0, 0.f); u1 = fmaxf(u1, 0.f);
                    float x0 = h0 + u0, x1 = h1 + u1;
                    float sums = x0 + x1;
                    #pragma unroll
                    for (int o = 16; o > 0; o >>= 1) sums += __shfl_xor_sync(FULL, sums, o);
                    float mean = sums * (1.f / 64.f);
                    float d0 = x0 - mean, d1 = x1 - mean;
                    float v = d0 * d0 + d1 * d1;
                    #pragma unroll
                    for (int o = 16; o > 0; o >>= 1) v += __shfl_xor_sync(FULL, v, o);
                    float inv = rsqrtf(v * (1.f / 64.f) + 1e-5f);
                    g_h[slot * DIM + lane]      = d0 * inv * lg0 + lb0;
                    g_h[slot * DIM + lane + 32] = d1 * inv * lg1 + lb1;
                    g_agg[slot * DIM + lane] = 0.f;
                    g_agg[slot * DIM + lane + 32] = 0.f;
                    __syncwarp();
                }
            }
        }
        bar_n(3 + 2 * l, nlb);
    }

    // ---------------- active scores -> scratch, join, scatter+clean -----------
    {
        for (int i = tid; i < 2 * DIM * 32; i += TPB) {
            int k = i >> 5, j = i & 31;
            sm.s.w[i] = make_float2(__ldg(&sW1[k * DIM + j]), __ldg(&sW1[k * DIM + j + 32]));
        }
        __syncthreads();
        float rb0 = __ldg(&sb1[lane]), rb1 = __ldg(&sb1[lane + 32]);
        float rv0 = __ldg(&sW2[lane]), rv1 = __ldg(&sW2[lane + 32]);
        float b2 = __ldg(&sb2[0]);

        int nAct = __ldcg(&g_cnt[1]);
        float4* teA = sm.s.te4[wl][0];
        float* tep = reinterpret_cast<float*>(teA);
        for (int idx = lwarp; idx < nAct; idx += lwarps) {
            int p = __ldcg(&g_nlist[idx]);
            int n = p >> 2, b = p & 3;
            int slot = __ldcg(&g_slotmap[b * NE + n]) - 1;
            tep[lane]      = __ldcg(&g_h[slot * DIM + lane]);
            tep[lane + 32] = __ldcg(&g_h[slot * DIM + lane + 32]);
            tep[64 + lane] = __ldg(&ent[n * DIM + lane]);
            tep[96 + lane] = __ldg(&ent[n * DIM + lane + 32]);
            __syncwarp();
            float s0 = rb0, s1 = rb1;
            #pragma unroll 8
            for (int k = 0; k < 2 * DIM; k++) {
                float xk = tep[k];
                float2 wv = sm.s.w[k * 32 + lane];
                s0 = fmaf(xk, wv.x, s0);
                s1 = fmaf(xk, wv.y, s1);
            }
            float a = fmaxf(s0, 0.f) * rv0 + fmaxf(s1, 0.f) * rv1;
            #pragma unroll
            for (int o = 16; o > 0; o >>= 1) a += __shfl_xor_sync(FULL, a, o);
            if (lane == 0) g_actscore[idx] = a + b2;   // staged, not out
            __syncwarp();
        }

        bar_n(8, nb);     // join: bg writes + staged scores visible everywhere
        scatter_and_clean(out, nAct, gt, gthreads);
    }

    // ---------------- final barrier (ALL blocks) + counter reset --------------
    __syncthreads();
    if (tid == 0) {
        __threadfence();
        atomicAdd(&g_bar[9], 1u);
    }
    if (bid == 0 && tid == 0) {
        while (*(volatile unsigned int*)&g_bar[9] < (unsigned)nb) __nanosleep(64);
        #pragma unroll
        for (int i = 0; i < 16; i++) g_bar[i] = 0u;
        #pragma unroll
        for (int i = 0; i < 8; i++) g_cnt[i] = 0;
    }
}

extern "C" void kernel_launch(void* const* d_in, const int* in_sizes, int n_in,
                              void* d_out, int out_size) {
    const float* ent   = (const float*)d_in[0];
    const float* qemb  = (const float*)d_in[1];
    const float* rele  = (const float*)d_in[2];
    const float* msgW  = (const float*)d_in[3];
    const float* gateW = (const float*)d_in[4];
    const float* updW  = (const float*)d_in[5];
    const float* updb  = (const float*)d_in[6];
    const float* lng   = (const float*)d_in[7];
    const float* lnb   = (const float*)d_in[8];
    const float* sW1   = (const float*)d_in[9];
    const float* sb1   = (const float*)d_in[10];
    const float* sW2   = (const float*)d_in[11];
    const float* sb2   = (const float*)d_in[12];
    const int* source  = (const int*)d_in[13];
    const int* qrel    = (const int*)d_in[14];
    const int* esrc    = (const int*)d_in[15];
    const int* etgt    = (const int*)d_in[16];
    const int* erel    = (const int*)d_in[17];
    float* out = (float*)d_out;

    int dev = 0;
    cudaGetDevice(&dev);
    int sms = 0;
    cudaDeviceGetAttribute(&sms, cudaDevAttrMultiProcessorCount, dev);
    int maxb = 0;
    cudaOccupancyMaxActiveBlocksPerMultiprocessor(&maxb, k_all, TPB, 0);
    if (maxb < 1) maxb = 1;
    int grid = sms * maxb;

    k_all<<<grid, TPB>>>(ent, qemb, rele, msgW, gateW, updW, updb, lng, lnb,
                         sW1, sb1, sW2, sb2, source, qrel, esrc, etgt, erel, out);
}

// round 16
// speedup vs baseline: 1.5794x; 1.0423x over previous
#include <cuda_runtime.h>
#include <math.h>

#define NE      50000
#define DIM     64
#define NREL    400
#define NLAYERS 3
#define BS      4
#define NEDGE   400000
#define MAXSLOTS (BS * NE)
#define FULL 0xffffffffu
#define TPB 256
#define WPB (TPB / 32)

// ---------------- persistent device scratch (static, no allocation) ----------
// Invariant: slotmap/mask/cnt/bar are ALL-ZERO at kernel entry. Guaranteed by
// the loader on first launch and by the epilogue cleanup on every launch.
__device__ float        g_h[MAXSLOTS * DIM];
__device__ float        g_agg[MAXSLOTS * DIM];
__device__ float        g_actscore[MAXSLOTS];    // staged active scores
__device__ int          g_slotmap[BS * NE];      // slot+1, 0 = free, -1 = claiming
__device__ unsigned int g_mask[NE];              // bit b = (b,node) active
__device__ int          g_elist[BS * NEDGE];     // packed (edge<<2)|b
__device__ int          g_nlist[MAXSLOTS];       // packed (node<<2)|b
__device__ int          g_cnt[8];                // 0 slots, 1 nlist, 2+l edges/layer
__device__ unsigned int g_bar[16];               // barrier counters

struct SMemMsg { float M[DIM * DIM]; float G[DIM * DIM]; float sh[WPB][DIM]; };
struct SMemUpd { float W[2 * DIM * DIM]; float x[WPB][2 * DIM]; };
struct SMemSc  { float2 w[2 * DIM * 32]; float4 te4[WPB][2][DIM]; };
union SMemAll { SMemMsg m; SMemUpd u; SMemSc s; };

// Barrier over `count` blocks (arrivals strictly one per participating block).
__device__ __forceinline__ void bar_n(int i, unsigned count) {
    __syncthreads();
    if (threadIdx.x == 0) {
        __threadfence();
        atomicAdd(&g_bar[i], 1u);
        while (*(volatile unsigned int*)&g_bar[i] < count) __nanosleep(64);
    }
    __syncthreads();
}

// Warp-aggregated append of active (edge,batch) pairs into g_elist.
// Caller guarantees at least one lane has a nonzero mask (ballot pre-check).
__device__ __forceinline__ void push4(int base, const unsigned mm[4], int cslot, int lane) {
    int cnt = __popc(mm[0]) + __popc(mm[1]) + __popc(mm[2]) + __popc(mm[3]);
    int x = cnt;
    #pragma unroll
    for (int o = 1; o < 32; o <<= 1) {
        int y = __shfl_up_sync(FULL, x, o);
        if (lane >= o) x += y;
    }
    int warpTotal = __shfl_sync(FULL, x, 31);
    int basePos = 0;
    if (lane == 31) basePos = atomicAdd(&g_cnt[cslot], warpTotal);
    basePos = __shfl_sync(FULL, basePos, 31);
    int pos = basePos + x - cnt;
    #pragma unroll
    for (int j = 0; j < 4; j++) {
        unsigned m = mm[j];
        while (m) {
            int b = __ffs((int)m) - 1;
            m &= m - 1;
            g_elist[pos++] = ((base + j) << 2) | b;
        }
    }
}

__device__ __forceinline__ void scan_layer(const int* __restrict__ esrc, int layer,
                                           int gwarp, int gwarps, int lane) {
    const int CW = NEDGE / 4 / 32;   // 3125
    for (int cw = gwarp; cw < CW; cw += gwarps) {
        int base = (cw * 32 + lane) * 4;
        int4 e4 = *reinterpret_cast<const int4*>(esrc + base);
        unsigned mm[4];
        mm[0] = __ldcg(&g_mask[e4.x]);
        mm[1] = __ldcg(&g_mask[e4.y]);
        mm[2] = __ldcg(&g_mask[e4.z]);
        mm[3] = __ldcg(&g_mask[e4.w]);
        // fast path: whole warp empty -> skip prefix scan entirely
        if (__ballot_sync(FULL, (mm[0] | mm[1] | mm[2] | mm[3]) != 0u) == 0u) continue;
        push4(base, mm, 2 + layer, lane);
    }
}

// Background score for 8 nodes per item, written unconditionally to all batches.
__device__ __forceinline__ void bg_score(SMemAll& sm, const float* __restrict__ ent,
                                         float* __restrict__ out,
                                         float rb0, float rb1, float rv0, float rv1,
                                         float b2, int wl, int lane,
                                         int warp0, int warps) {
    const int nBg = NE / 8;   // 6250
    float4* teA = sm.s.te4[wl][0];
    float4* teB = sm.s.te4[wl][1];
    for (int w = warp0; w < nBg; w += warps) {
        int n0 = w * 8;
        float v0 = __ldg(&ent[(n0 + 0) * DIM + lane]);
        float v1 = __ldg(&ent[(n0 + 1) * DIM + lane]);
        float v2 = __ldg(&ent[(n0 + 2) * DIM + lane]);
        float v3 = __ldg(&ent[(n0 + 3) * DIM + lane]);
        float v4 = __ldg(&ent[(n0 + 4) * DIM + lane]);
        float v5 = __ldg(&ent[(n0 + 5) * DIM + lane]);
        float v6 = __ldg(&ent[(n0 + 6) * DIM + lane]);
        float v7 = __ldg(&ent[(n0 + 7) * DIM + lane]);
        float u0 = __ldg(&ent[(n0 + 0) * DIM + lane + 32]);
        float u1 = __ldg(&ent[(n0 + 1) * DIM + lane + 32]);
        float u2 = __ldg(&ent[(n0 + 2) * DIM + lane + 32]);
        float u3 = __ldg(&ent[(n0 + 3) * DIM + lane + 32]);
        float u4 = __ldg(&ent[(n0 + 4) * DIM + lane + 32]);
        float u5 = __ldg(&ent[(n0 + 5) * DIM + lane + 32]);
        float u6 = __ldg(&ent[(n0 + 6) * DIM + lane + 32]);
        float u7 = __ldg(&ent[(n0 + 7) * DIM + lane + 32]);
        teA[lane]      = make_float4(v0, v1, v2, v3);
        teA[lane + 32] = make_float4(u0, u1, u2, u3);
        teB[lane]      = make_float4(v4, v5, v6, v7);
        teB[lane + 32] = make_float4(u4, u5, u6, u7);
        __syncwarp();
        float s0[8], s1[8];
        #pragma unroll
        for (int j = 0; j < 8; j++) { s0[j] = rb0; s1[j] = rb1; }
        #pragma unroll 4
        for (int k = 0; k < DIM; k++) {
            float2 wv = sm.s.w[(DIM + k) * 32 + lane];
            float4 a = teA[k];
            float4 b = teB[k];
            s0[0] = fmaf(a.x, wv.x, s0[0]); s1[0] = fmaf(a.x, wv.y, s1[0]);
            s0[1] = fmaf(a.y, wv.x, s0[1]); s1[1] = fmaf(a.y, wv.y, s1[1]);
            s0[2] = fmaf(a.z, wv.x, s0[2]); s1[2] = fmaf(a.z, wv.y, s1[2]);
            s0[3] = fmaf(a.w, wv.x, s0[3]); s1[3] = fmaf(a.w, wv.y, s1[3]);
            s0[4] = fmaf(b.x, wv.x, s0[4]); s1[4] = fmaf(b.x, wv.y, s1[4]);
            s0[5] = fmaf(b.y, wv.x, s0[5]); s1[5] = fmaf(b.y, wv.y, s1[5]);
            s0[6] = fmaf(b.z, wv.x, s0[6]); s1[6] = fmaf(b.z, wv.y, s1[6]);
            s0[7] = fmaf(b.w, wv.x, s0[7]); s1[7] = fmaf(b.w, wv.y, s1[7]);
        }
        float sc[8];
        #pragma unroll
        for (int j = 0; j < 8; j++) {
            float a = fmaxf(s0[j], 0.f) * rv0 + fmaxf(s1[j], 0.f) * rv1;
            #pragma unroll
            for (int o = 16; o > 0; o >>= 1) a += __shfl_xor_sync(FULL, a, o);
            sc[j] = a + b2;
        }
        if (lane == 0) {
            float4 va = make_float4(sc[0], sc[1], sc[2], sc[3]);
            float4 vb = make_float4(sc[4], sc[5], sc[6], sc[7]);
            #pragma unroll
            for (int b = 0; b < BS; b++) {
                *reinterpret_cast<float4*>(&out[b * NE + n0])     = va;
                *reinterpret_cast<float4*>(&out[b * NE + n0 + 4]) = vb;
            }
        }
        __syncwarp();
    }
}

// Post-join: scatter staged active scores AND restore the zero invariant for
// the entries this thread touches (disjoint arrays; both safe after bar8).
__device__ __forceinline__ void scatter_and_clean(float* __restrict__ out,
                                                  int nAct, int gt, int gthreads) {
    for (int i = gt; i < nAct; i += gthreads) {
        int p = __ldcg(&g_nlist[i]);
        int n = p >> 2, b = p & 3;
        out[b * NE + n] = __ldcg(&g_actscore[i]);
        g_slotmap[b * NE + n] = 0;
        g_mask[n] = 0u;           // duplicate writes across b are benign
    }
}

__global__ void __launch_bounds__(TPB, 2)
k_all(const float* __restrict__ ent, const float* __restrict__ qemb,
      const float* __restrict__ rele, const float* __restrict__ msgW,
      const float* __restrict__ gateW, const float* __restrict__ updW,
      const float* __restrict__ updb, const float* __restrict__ lng,
      const float* __restrict__ lnb, const float* __restrict__ sW1,
      const float* __restrict__ sb1, const float* __restrict__ sW2,
      const float* __restrict__ sb2, const int* __restrict__ source,
      const int* __restrict__ qrel, const int* __restrict__ esrc,
      const int* __restrict__ etgt, const int* __restrict__ erel,
      float* __restrict__ out) {
    __shared__ SMemAll sm;
    const int tid  = threadIdx.x;
    const int lane = tid & 31;
    const int wl   = tid >> 5;
    const int bid  = blockIdx.x;
    const int nb   = gridDim.x;
    const int pbg  = nb / 3;                // bg-score blocks
    const int nlb  = nb - pbg;              // layer-pipeline blocks
    const bool isLayer = bid < nlb;
    const int gthreads = nb * TPB;
    const int gwarps   = gthreads >> 5;
    const int gwarp    = bid * WPB + wl;
    const int gt       = bid * TPB + tid;
    const int lwarps   = nlb * WPB;
    const int lwarp    = gwarp;             // valid for layer blocks only

    // ---------------- P0: scan layer-0 + seed + weight preload ----------------
    {
        if (isLayer) {
            for (int i = tid; i < DIM * DIM; i += TPB) {
                sm.m.M[i] = __ldg(&msgW[i]);        // layer 0
                sm.m.G[i] = __ldg(&gateW[i]);
            }
        } else {
            for (int i = tid; i < 2 * DIM * 32; i += TPB) {
                int k = i >> 5, j = i & 31;
                sm.s.w[i] = make_float2(__ldg(&sW1[k * DIM + j]), __ldg(&sW1[k * DIM + j + 32]));
            }
        }

        if (bid == 0) {
            if (wl < BS) {
                int n = __ldg(&source[wl]);
                int r = __ldg(&qrel[wl]);
                if (lane == 0) {
                    g_slotmap[wl * NE + n] = wl + 1;
                    atomicOr(&g_mask[n], 1u << wl);
                    g_nlist[wl] = (n << 2) | wl;
                }
                g_h[wl * DIM + lane]      = __ldg(&ent[n * DIM + lane])      + __ldg(&qemb[r * DIM + lane]);
                g_h[wl * DIM + lane + 32] = __ldg(&ent[n * DIM + lane + 32]) + __ldg(&qemb[r * DIM + lane + 32]);
                g_agg[wl * DIM + lane] = 0.f;
                g_agg[wl * DIM + lane + 32] = 0.f;
            }
            if (tid == 0) { g_cnt[0] = BS; g_cnt[1] = BS; }
        }

        int s0 = __ldg(&source[0]), s1 = __ldg(&source[1]);
        int s2 = __ldg(&source[2]), s3 = __ldg(&source[3]);
        const int CW = NEDGE / 4 / 32;
        for (int cw = gwarp; cw < CW; cw += gwarps) {
            int base = (cw * 32 + lane) * 4;
            int4 e4 = *reinterpret_cast<const int4*>(esrc + base);
            unsigned mm[4];
            mm[0] = (unsigned)(e4.x == s0) | ((unsigned)(e4.x == s1) << 1) |
                    ((unsigned)(e4.x == s2) << 2) | ((unsigned)(e4.x == s3) << 3);
            mm[1] = (unsigned)(e4.y == s0) | ((unsigned)(e4.y == s1) << 1) |
                    ((unsigned)(e4.y == s2) << 2) | ((unsigned)(e4.y == s3) << 3);
            mm[2] = (unsigned)(e4.z == s0) | ((unsigned)(e4.z == s1) << 1) |
                    ((unsigned)(e4.z == s2) << 2) | ((unsigned)(e4.z == s3) << 3);
            mm[3] = (unsigned)(e4.w == s0) | ((unsigned)(e4.w == s1) << 1) |
                    ((unsigned)(e4.w == s2) << 2) | ((unsigned)(e4.w == s3) << 3);
            if (__ballot_sync(FULL, (mm[0] | mm[1] | mm[2] | mm[3]) != 0u) == 0u) continue;
            push4(base, mm, 2, lane);
        }
    }
    bar_n(0, nb);

    // ---------------- bg-score blocks ------------------------------------------
    if (!isLayer) {
        float rb0 = __ldg(&sb1[lane]), rb1 = __ldg(&sb1[lane + 32]);
        float rv0 = __ldg(&sW2[lane]), rv1 = __ldg(&sW2[lane + 32]);
        float b2 = __ldg(&sb2[0]);
        bg_score(sm, ent, out, rb0, rb1, rv0, rv1, b2, wl, lane,
                 (bid - nlb) * WPB + wl, pbg * WPB);
        bar_n(8, nb);           // join: bg + actscore writes globally visible
        int nAct = __ldcg(&g_cnt[1]);
        scatter_and_clean(out, nAct, gt, gthreads);
        __syncthreads();
        if (tid == 0) { __threadfence(); atomicAdd(&g_bar[9], 1u); }
        return;
    }

    // ========================= layer pipeline (nlb blocks) ====================
    for (int l = 0; l < NLAYERS; l++) {
        // ---- msg(l) ----
        {
            int total = __ldcg(&g_cnt[2 + l]);
            int pb = min(nlb, max(1, (total + WPB - 1) / WPB));
            if (bid < pb) {
                if (l > 0) {     // layer-0 weights preloaded in P0
                    for (int i = tid; i < DIM * DIM; i += TPB) {
                        sm.m.M[i] = __ldg(&msgW[l * DIM * DIM + i]);
                        sm.m.G[i] = __ldg(&gateW[l * DIM * DIM + i]);
                    }
                    __syncthreads();
                }
                for (int idx = bid * WPB + wl; idx < total; idx += pb * WPB) {
                    int p = __ldcg(&g_elist[idx]);
                    int e = p >> 2, b = p & 3;
                    int s = __ldg(&esrc[e]), t = __ldg(&etgt[e]), r = __ldg(&erel[e]);
                    int ss = __ldcg(&g_slotmap[b * NE + s]) - 1;

                    int* sp = &g_slotmap[b * NE + t];
                    int cur;
                    if (lane == 0) cur = atomicCAS(sp, 0, -1);
                    cur = __shfl_sync(FULL, cur, 0);
                    int ts;
                    if (cur == 0) {
                        int slot;
                        if (lane == 0) slot = atomicAdd(&g_cnt[0], 1);
                        slot = __shfl_sync(FULL, slot, 0);
                        g_h[slot * DIM + lane] = 0.f;       g_h[slot * DIM + lane + 32] = 0.f;
                        g_agg[slot * DIM + lane] = 0.f;     g_agg[slot * DIM + lane + 32] = 0.f;
                        __syncwarp();
                        __threadfence();
                        if (lane == 0) {
                            int ni = atomicAdd(&g_cnt[1], 1);
                            g_nlist[ni] = (t << 2) | b;
                            atomicOr(&g_mask[t], 1u << b);
                            atomicExch(sp, slot + 1);
                        }
                        ts = slot;
                    } else if (cur > 0) {
                        ts = cur - 1;
                    } else {
                        if (lane == 0) { do { cur = atomicAdd(sp, 0); } while (cur <= 0); }
                        cur = __shfl_sync(FULL, cur, 0);
                        ts = cur - 1;
                    }

                    sm.m.sh[wl][lane]      = __ldcg(&g_h[ss * DIM + lane]);
                    sm.m.sh[wl][lane + 32] = __ldcg(&g_h[ss * DIM + lane + 32]);
                    __syncwarp();
                    float m0 = 0.f, m1 = 0.f, q0 = 0.f, q1 = 0.f;
                    #pragma unroll 8
                    for (int k = 0; k < DIM; k++) {
                        float hk = sm.m.sh[wl][k];
                        m0 = fmaf(hk, sm.m.M[k * DIM + lane],      m0);
                        m1 = fmaf(hk, sm.m.M[k * DIM + lane + 32], m1);
                        q0 = fmaf(hk, sm.m.G[k * DIM + lane],      q0);
                        q1 = fmaf(hk, sm.m.G[k * DIM + lane + 32], q1);
                    }
                    const float* rr = rele + (size_t)(l * NREL + r) * DIM;
                    float v0 = __ldg(&rr[lane])      * m0 * (1.f / (1.f + expf(-q0)));
                    float v1 = __ldg(&rr[lane + 32]) * m1 * (1.f / (1.f + expf(-q1)));
                    atomicAdd(&g_agg[ts * DIM + lane],      v0);
                    atomicAdd(&g_agg[ts * DIM + lane + 32], v1);
                    __syncwarp();
                }
            }
        }
        bar_n(2 + 2 * l, nlb);

        // ---- scan(l+1) (layer warps) ----
        if (l + 1 < NLAYERS) scan_layer(esrc, l + 1, lwarp, lwarps, lane);

        // ---- update(l); for the LAST layer the final score is fused in ----
        {
            int total = __ldcg(&g_cnt[1]);
            int pb = min(nlb, max(1, (total + WPB - 1) / WPB));
            if (bid < pb) {
                for (int i = tid; i < 2 * DIM * DIM; i += TPB)
                    sm.u.W[i] = __ldg(&updW[l * 2 * DIM * DIM + i]);
                __syncthreads();
                float ub0 = __ldg(&updb[l * DIM + lane]), ub1 = __ldg(&updb[l * DIM + lane + 32]);
                float lg0 = __ldg(&lng[l * DIM + lane]),  lg1 = __ldg(&lng[l * DIM + lane + 32]);
                float lb0 = __ldg(&lnb[l * DIM + lane]),  lb1 = __ldg(&lnb[l * DIM + lane + 32]);
                // score constants (used only when l is the last layer)
                float rb0 = __ldg(&sb1[lane]), rb1 = __ldg(&sb1[lane + 32]);
                float rv0 = __ldg(&sW2[lane]), rv1 = __ldg(&sW2[lane + 32]);
                float b2 = __ldg(&sb2[0]);
                for (int idx = bid * WPB + wl; idx < total; idx += pb * WPB) {
                    int p = __ldcg(&g_nlist[idx]);
                    int n = p >> 2, b = p & 3;
                    int slot = __ldcg(&g_slotmap[b * NE + n]) - 1;
                    float h0 = __ldcg(&g_h[slot * DIM + lane]);
                    float h1 = __ldcg(&g_h[slot * DIM + lane + 32]);
                    float a0 = __ldcg(&g_agg[slot * DIM + lane]);
                    float a1 = __ldcg(&g_agg[slot * DIM + lane + 32]);
                    sm.u.x[wl][lane] = h0;      sm.u.x[wl][lane + 32] = h1;
                    sm.u.x[wl][64 + lane] = a0; sm.u.x[wl][96 + lane] = a1;
                    __syncwarp();
                    float u0 = ub0, u1 = ub1;
                    #pragma unroll 8
                    for (int k = 0; k < 2 * DIM; k++) {
                        float xk = sm.u.x[wl][k];
                        u0 = fmaf(xk, sm.u.W[k * DIM + lane],      u0);
                        u1 = fmaf(xk, sm.u.W[k * DIM + lane + 32], u1);
                    }
                    u0 = fmaxf(u0, 0.f); u1 = fmaxf(u1, 0.f);
                    float x0 = h0 + u0, x1 = h1 + u1;
                    float sums = x0 + x1;
                    #pragma unroll
                    for (int o = 16; o > 0; o >>= 1) sums += __shfl_xor_sync(FULL, sums, o);
                    float mean = sums * (1.f / 64.f);
                    float d0 = x0 - mean, d1 = x1 - mean;
                    float v = d0 * d0 + d1 * d1;
                    #pragma unroll
                    for (int o = 16; o > 0; o >>= 1) v += __shfl_xor_sync(FULL, v, o);
                    float inv = rsqrtf(v * (1.f / 64.f) + 1e-5f);
                    float nh0 = d0 * inv * lg0 + lb0;
                    float nh1 = d1 * inv * lg1 + lb1;
                    if (l < NLAYERS - 1) {
                        g_h[slot * DIM + lane]      = nh0;
                        g_h[slot * DIM + lane + 32] = nh1;
                        g_agg[slot * DIM + lane] = 0.f;
                        g_agg[slot * DIM + lane + 32] = 0.f;
                        __syncwarp();
                    } else {
                        // --- fused final score: x = [h_new, ent[n]] @ sW1 ---
                        // sW1 read via __ldg: L1-resident after the first item per SM.
                        sm.u.x[wl][lane]      = nh0;
                        sm.u.x[wl][lane + 32] = nh1;
                        sm.u.x[wl][64 + lane] = __ldg(&ent[n * DIM + lane]);
                        sm.u.x[wl][96 + lane] = __ldg(&ent[n * DIM + lane + 32]);
                        __syncwarp();
                        float s0 = rb0, s1 = rb1;
                        #pragma unroll 8
                        for (int k = 0; k < 2 * DIM; k++) {
                            float xk = sm.u.x[wl][k];
                            s0 = fmaf(xk, __ldg(&sW1[k * DIM + lane]),      s0);
                            s1 = fmaf(xk, __ldg(&sW1[k * DIM + lane + 32]), s1);
                        }
                        float a = fmaxf(s0, 0.f) * rv0 + fmaxf(s1, 0.f) * rv1;
                        #pragma unroll
                        for (int o = 16; o > 0; o >>= 1) a += __shfl_xor_sync(FULL, a, o);
                        if (lane == 0) g_actscore[idx] = a + b2;
                        __syncwarp();
                    }
                }
            }
        }
        if (l < NLAYERS - 1) bar_n(3 + 2 * l, nlb);   // last layer: bar8 is the join
    }

    // ---------------- join, scatter+clean --------------------------------------
    {
        bar_n(8, nb);     // join: bg writes + staged scores visible everywhere
        int nAct = __ldcg(&g_cnt[1]);
        scatter_and_clean(out, nAct, gt, gthreads);
    }

    // ---------------- final barrier (ALL blocks) + counter reset --------------
    __syncthreads();
    if (tid == 0) {
        __threadfence();
        atomicAdd(&g_bar[9], 1u);
    }
    if (bid == 0 && tid == 0) {
        while (*(volatile unsigned int*)&g_bar[9] < (unsigned)nb) __nanosleep(64);
        #pragma unroll
        for (int i = 0; i < 16; i++) g_bar[i] = 0u;
        #pragma unroll
        for (int i = 0; i < 8; i++) g_cnt[i] = 0;
    }
}

extern "C" void kernel_launch(void* const* d_in, const int* in_sizes, int n_in,
                              void* d_out, int out_size) {
    const float* ent   = (const float*)d_in[0];
    const float* qemb  = (const float*)d_in[1];
    const float* rele  = (const float*)d_in[2];
    const float* msgW  = (const float*)d_in[3];
    const float* gateW = (const float*)d_in[4];
    const float* updW  = (const float*)d_in[5];
    const float* updb  = (const float*)d_in[6];
    const float* lng   = (const float*)d_in[7];
    const float* lnb   = (const float*)d_in[8];
    const float* sW1   = (const float*)d_in[9];
    const float* sb1   = (const float*)d_in[10];
    const float* sW2   = (const float*)d_in[11];
    const float* sb2   = (const float*)d_in[12];
    const int* source  = (const int*)d_in[13];
    const int* qrel    = (const int*)d_in[14];
    const int* esrc    = (const int*)d_in[15];
    const int* etgt    = (const int*)d_in[16];
    const int* erel    = (const int*)d_in[17];
    float* out = (float*)d_out;

    int dev = 0;
    cudaGetDevice(&dev);
    int sms = 0;
    cudaDeviceGetAttribute(&sms, cudaDevAttrMultiProcessorCount, dev);
    int maxb = 0;
    cudaOccupancyMaxActiveBlocksPerMultiprocessor(&maxb, k_all, TPB, 0);
    if (maxb < 1) maxb = 1;
    int grid = sms * maxb;

    k_all<<<grid, TPB>>>(ent, qemb, rele, msgW, gateW, updW, updb, lng, lnb,
                         sW1, sb1, sW2, sb2, source, qrel, esrc, etgt, erel, out);
}

// round 17
// speedup vs baseline: 1.6469x; 1.0427x over previous
#include <cuda_runtime.h>
#include <math.h>

#define NE      50000
#define DIM     64
#define NREL    400
#define NLAYERS 3
#define BS      4
#define NEDGE   400000
#define MAXSLOTS (BS * NE)
#define FULL 0xffffffffu
#define TPB 256
#define WPB (TPB / 32)

// ---------------- persistent device scratch (static, no allocation) ----------
// Invariant: slotmap/mask/cnt/bar are ALL-ZERO at kernel entry. Guaranteed by
// the loader on first launch and by the epilogue cleanup on every launch.
__device__ float        g_h[MAXSLOTS * DIM];
__device__ float        g_agg[MAXSLOTS * DIM];
__device__ float        g_actscore[MAXSLOTS];    // staged active scores
__device__ int          g_slotmap[BS * NE];      // slot+1, 0 = free, -1 = claiming
__device__ unsigned int g_mask[NE];              // bit b = (b,node) active
__device__ int          g_elist[BS * NEDGE];     // packed (edge<<2)|b
__device__ int          g_nlist[MAXSLOTS];       // packed (node<<2)|b
__device__ int          g_cnt[8];                // 0 slots, 1 nlist, 2+l edges/layer
__device__ unsigned int g_bar[16];               // barrier counters

struct SMemMsg { float M[DIM * DIM]; float G[DIM * DIM]; float sh[WPB][DIM]; };
struct SMemUpd { float W[2 * DIM * DIM]; float x[WPB][2 * DIM]; };
struct SMemPipe { SMemMsg m; SMemUpd u; };       // de-unioned: both live at once
struct SMemSc  { float2 w[2 * DIM * 32]; float4 te4[WPB][2][DIM]; };
union SMemAll { SMemPipe p; SMemSc s; };

// Barrier over `count` blocks (arrivals strictly one per participating block).
__device__ __forceinline__ void bar_n(int i, unsigned count) {
    __syncthreads();
    if (threadIdx.x == 0) {
        __threadfence();
        atomicAdd(&g_bar[i], 1u);
        while (*(volatile unsigned int*)&g_bar[i] < count) __nanosleep(64);
    }
    __syncthreads();
}

// Warp-aggregated append of active (edge,batch) pairs into g_elist.
// Caller guarantees at least one lane has a nonzero mask (ballot pre-check).
__device__ __forceinline__ void push4(int base, const unsigned mm[4], int cslot, int lane) {
    int cnt = __popc(mm[0]) + __popc(mm[1]) + __popc(mm[2]) + __popc(mm[3]);
    int x = cnt;
    #pragma unroll
    for (int o = 1; o < 32; o <<= 1) {
        int y = __shfl_up_sync(FULL, x, o);
        if (lane >= o) x += y;
    }
    int warpTotal = __shfl_sync(FULL, x, 31);
    int basePos = 0;
    if (lane == 31) basePos = atomicAdd(&g_cnt[cslot], warpTotal);
    basePos = __shfl_sync(FULL, basePos, 31);
    int pos = basePos + x - cnt;
    #pragma unroll
    for (int j = 0; j < 4; j++) {
        unsigned m = mm[j];
        while (m) {
            int b = __ffs((int)m) - 1;
            m &= m - 1;
            g_elist[pos++] = ((base + j) << 2) | b;
        }
    }
}

__device__ __forceinline__ void scan_layer(const int* __restrict__ esrc, int layer,
                                           int gwarp, int gwarps, int lane) {
    const int CW = NEDGE / 4 / 32;   // 3125
    for (int cw = gwarp; cw < CW; cw += gwarps) {
        int base = (cw * 32 + lane) * 4;
        int4 e4 = *reinterpret_cast<const int4*>(esrc + base);
        unsigned mm[4];
        mm[0] = __ldcg(&g_mask[e4.x]);
        mm[1] = __ldcg(&g_mask[e4.y]);
        mm[2] = __ldcg(&g_mask[e4.z]);
        mm[3] = __ldcg(&g_mask[e4.w]);
        // fast path: whole warp empty -> skip prefix scan entirely
        if (__ballot_sync(FULL, (mm[0] | mm[1] | mm[2] | mm[3]) != 0u) == 0u) continue;
        push4(base, mm, 2 + layer, lane);
    }
}

// Background score for 8 nodes per item, written unconditionally to all batches.
__device__ __forceinline__ void bg_score(SMemAll& sm, const float* __restrict__ ent,
                                         float* __restrict__ out,
                                         float rb0, float rb1, float rv0, float rv1,
                                         float b2, int wl, int lane,
                                         int warp0, int warps) {
    const int nBg = NE / 8;   // 6250
    float4* teA = sm.s.te4[wl][0];
    float4* teB = sm.s.te4[wl][1];
    for (int w = warp0; w < nBg; w += warps) {
        int n0 = w * 8;
        float v0 = __ldg(&ent[(n0 + 0) * DIM + lane]);
        float v1 = __ldg(&ent[(n0 + 1) * DIM + lane]);
        float v2 = __ldg(&ent[(n0 + 2) * DIM + lane]);
        float v3 = __ldg(&ent[(n0 + 3) * DIM + lane]);
        float v4 = __ldg(&ent[(n0 + 4) * DIM + lane]);
        float v5 = __ldg(&ent[(n0 + 5) * DIM + lane]);
        float v6 = __ldg(&ent[(n0 + 6) * DIM + lane]);
        float v7 = __ldg(&ent[(n0 + 7) * DIM + lane]);
        float u0 = __ldg(&ent[(n0 + 0) * DIM + lane + 32]);
        float u1 = __ldg(&ent[(n0 + 1) * DIM + lane + 32]);
        float u2 = __ldg(&ent[(n0 + 2) * DIM + lane + 32]);
        float u3 = __ldg(&ent[(n0 + 3) * DIM + lane + 32]);
        float u4 = __ldg(&ent[(n0 + 4) * DIM + lane + 32]);
        float u5 = __ldg(&ent[(n0 + 5) * DIM + lane + 32]);
        float u6 = __ldg(&ent[(n0 + 6) * DIM + lane + 32]);
        float u7 = __ldg(&ent[(n0 + 7) * DIM + lane + 32]);
        teA[lane]      = make_float4(v0, v1, v2, v3);
        teA[lane + 32] = make_float4(u0, u1, u2, u3);
        teB[lane]      = make_float4(v4, v5, v6, v7);
        teB[lane + 32] = make_float4(u4, u5, u6, u7);
        __syncwarp();
        float s0[8], s1[8];
        #pragma unroll
        for (int j = 0; j < 8; j++) { s0[j] = rb0; s1[j] = rb1; }
        #pragma unroll 4
        for (int k = 0; k < DIM; k++) {
            float2 wv = sm.s.w[(DIM + k) * 32 + lane];
            float4 a = teA[k];
            float4 b = teB[k];
            s0[0] = fmaf(a.x, wv.x, s0[0]); s1[0] = fmaf(a.x, wv.y, s1[0]);
            s0[1] = fmaf(a.y, wv.x, s0[1]); s1[1] = fmaf(a.y, wv.y, s1[1]);
            s0[2] = fmaf(a.z, wv.x, s0[2]); s1[2] = fmaf(a.z, wv.y, s1[2]);
            s0[3] = fmaf(a.w, wv.x, s0[3]); s1[3] = fmaf(a.w, wv.y, s1[3]);
            s0[4] = fmaf(b.x, wv.x, s0[4]); s1[4] = fmaf(b.x, wv.y, s1[4]);
            s0[5] = fmaf(b.y, wv.x, s0[5]); s1[5] = fmaf(b.y, wv.y, s1[5]);
            s0[6] = fmaf(b.z, wv.x, s0[6]); s1[6] = fmaf(b.z, wv.y, s1[6]);
            s0[7] = fmaf(b.w, wv.x, s0[7]); s1[7] = fmaf(b.w, wv.y, s1[7]);
        }
        float sc[8];
        #pragma unroll
        for (int j = 0; j < 8; j++) {
            float a = fmaxf(s0[j], 0.f) * rv0 + fmaxf(s1[j], 0.f) * rv1;
            #pragma unroll
            for (int o = 16; o > 0; o >>= 1) a += __shfl_xor_sync(FULL, a, o);
            sc[j] = a + b2;
        }
        if (lane == 0) {
            float4 va = make_float4(sc[0], sc[1], sc[2], sc[3]);
            float4 vb = make_float4(sc[4], sc[5], sc[6], sc[7]);
            #pragma unroll
            for (int b = 0; b < BS; b++) {
                *reinterpret_cast<float4*>(&out[b * NE + n0])     = va;
                *reinterpret_cast<float4*>(&out[b * NE + n0 + 4]) = vb;
            }
        }
        __syncwarp();
    }
}

// Post-join: scatter staged active scores AND restore the zero invariant for
// the entries this thread touches (disjoint arrays; both safe after bar8).
__device__ __forceinline__ void scatter_and_clean(float* __restrict__ out,
                                                  int nAct, int gt, int gthreads) {
    for (int i = gt; i < nAct; i += gthreads) {
        int p = __ldcg(&g_nlist[i]);
        int n = p >> 2, b = p & 3;
        out[b * NE + n] = __ldcg(&g_actscore[i]);
        g_slotmap[b * NE + n] = 0;
        g_mask[n] = 0u;           // duplicate writes across b are benign
    }
}

__global__ void __launch_bounds__(TPB, 2)
k_all(const float* __restrict__ ent, const float* __restrict__ qemb,
      const float* __restrict__ rele, const float* __restrict__ msgW,
      const float* __restrict__ gateW, const float* __restrict__ updW,
      const float* __restrict__ updb, const float* __restrict__ lng,
      const float* __restrict__ lnb, const float* __restrict__ sW1,
      const float* __restrict__ sb1, const float* __restrict__ sW2,
      const float* __restrict__ sb2, const int* __restrict__ source,
      const int* __restrict__ qrel, const int* __restrict__ esrc,
      const int* __restrict__ etgt, const int* __restrict__ erel,
      float* __restrict__ out) {
    extern __shared__ char smraw[];
    SMemAll& sm = *reinterpret_cast<SMemAll*>(smraw);
    const int tid  = threadIdx.x;
    const int lane = tid & 31;
    const int wl   = tid >> 5;
    const int bid  = blockIdx.x;
    const int nb   = gridDim.x;
    const int pbg  = nb / 4;                // bg-score blocks
    const int nlb  = nb - pbg;              // layer-pipeline blocks
    const bool isLayer = bid < nlb;
    const int gthreads = nb * TPB;
    const int gwarps   = gthreads >> 5;
    const int gwarp    = bid * WPB + wl;
    const int gt       = bid * TPB + tid;
    const int lwarps   = nlb * WPB;
    const int lwarp    = gwarp;             // valid for layer blocks only

    // ---------------- P0: scan layer-0 + seed + weight preload ----------------
    {
        if (isLayer) {
            // preload BOTH layer-0 weight sets (msg + upd) under the scan's shadow
            for (int i = tid; i < DIM * DIM; i += TPB) {
                sm.p.m.M[i] = __ldg(&msgW[i]);
                sm.p.m.G[i] = __ldg(&gateW[i]);
            }
            for (int i = tid; i < 2 * DIM * DIM; i += TPB)
                sm.p.u.W[i] = __ldg(&updW[i]);
        } else {
            for (int i = tid; i < 2 * DIM * 32; i += TPB) {
                int k = i >> 5, j = i & 31;
                sm.s.w[i] = make_float2(__ldg(&sW1[k * DIM + j]), __ldg(&sW1[k * DIM + j + 32]));
            }
        }

        if (bid == 0) {
            if (wl < BS) {
                int n = __ldg(&source[wl]);
                int r = __ldg(&qrel[wl]);
                if (lane == 0) {
                    g_slotmap[wl * NE + n] = wl + 1;
                    atomicOr(&g_mask[n], 1u << wl);
                    g_nlist[wl] = (n << 2) | wl;
                }
                g_h[wl * DIM + lane]      = __ldg(&ent[n * DIM + lane])      + __ldg(&qemb[r * DIM + lane]);
                g_h[wl * DIM + lane + 32] = __ldg(&ent[n * DIM + lane + 32]) + __ldg(&qemb[r * DIM + lane + 32]);
                g_agg[wl * DIM + lane] = 0.f;
                g_agg[wl * DIM + lane + 32] = 0.f;
            }
            if (tid == 0) { g_cnt[0] = BS; g_cnt[1] = BS; }
        }

        int s0 = __ldg(&source[0]), s1 = __ldg(&source[1]);
        int s2 = __ldg(&source[2]), s3 = __ldg(&source[3]);
        const int CW = NEDGE / 4 / 32;
        for (int cw = gwarp; cw < CW; cw += gwarps) {
            int base = (cw * 32 + lane) * 4;
            int4 e4 = *reinterpret_cast<const int4*>(esrc + base);
            unsigned mm[4];
            mm[0] = (unsigned)(e4.x == s0) | ((unsigned)(e4.x == s1) << 1) |
                    ((unsigned)(e4.x == s2) << 2) | ((unsigned)(e4.x == s3) << 3);
            mm[1] = (unsigned)(e4.y == s0) | ((unsigned)(e4.y == s1) << 1) |
                    ((unsigned)(e4.y == s2) << 2) | ((unsigned)(e4.y == s3) << 3);
            mm[2] = (unsigned)(e4.z == s0) | ((unsigned)(e4.z == s1) << 1) |
                    ((unsigned)(e4.z == s2) << 2) | ((unsigned)(e4.z == s3) << 3);
            mm[3] = (unsigned)(e4.w == s0) | ((unsigned)(e4.w == s1) << 1) |
                    ((unsigned)(e4.w == s2) << 2) | ((unsigned)(e4.w == s3) << 3);
            if (__ballot_sync(FULL, (mm[0] | mm[1] | mm[2] | mm[3]) != 0u) == 0u) continue;
            push4(base, mm, 2, lane);
        }
    }
    bar_n(0, nb);

    // ---------------- bg-score blocks ------------------------------------------
    if (!isLayer) {
        float rb0 = __ldg(&sb1[lane]), rb1 = __ldg(&sb1[lane + 32]);
        float rv0 = __ldg(&sW2[lane]), rv1 = __ldg(&sW2[lane + 32]);
        float b2 = __ldg(&sb2[0]);
        bg_score(sm, ent, out, rb0, rb1, rv0, rv1, b2, wl, lane,
                 (bid - nlb) * WPB + wl, pbg * WPB);
        bar_n(8, nb);           // join: bg + actscore writes globally visible
        int nAct = __ldcg(&g_cnt[1]);
        scatter_and_clean(out, nAct, gt, gthreads);
        __syncthreads();
        if (tid == 0) { __threadfence(); atomicAdd(&g_bar[9], 1u); }
        return;
    }

    // ========================= layer pipeline (nlb blocks) ====================
    for (int l = 0; l < NLAYERS; l++) {
        // ---- msg(l): bottom block range; weights already in sm.p.m ----
        {
            int total = __ldcg(&g_cnt[2 + l]);
            int pb = min(nlb, max(1, (total + WPB - 1) / WPB));
            if (bid < pb) {
                for (int idx = bid * WPB + wl; idx < total; idx += pb * WPB) {
                    int p = __ldcg(&g_elist[idx]);
                    int e = p >> 2, b = p & 3;
                    int s = __ldg(&esrc[e]), t = __ldg(&etgt[e]), r = __ldg(&erel[e]);
                    int ss = __ldcg(&g_slotmap[b * NE + s]) - 1;

                    int* sp = &g_slotmap[b * NE + t];
                    int cur;
                    if (lane == 0) cur = atomicCAS(sp, 0, -1);
                    cur = __shfl_sync(FULL, cur, 0);
                    int ts;
                    if (cur == 0) {
                        int slot;
                        if (lane == 0) slot = atomicAdd(&g_cnt[0], 1);
                        slot = __shfl_sync(FULL, slot, 0);
                        g_h[slot * DIM + lane] = 0.f;       g_h[slot * DIM + lane + 32] = 0.f;
                        g_agg[slot * DIM + lane] = 0.f;     g_agg[slot * DIM + lane + 32] = 0.f;
                        __syncwarp();
                        __threadfence();
                        if (lane == 0) {
                            int ni = atomicAdd(&g_cnt[1], 1);
                            g_nlist[ni] = (t << 2) | b;
                            atomicOr(&g_mask[t], 1u << b);
                            atomicExch(sp, slot + 1);
                        }
                        ts = slot;
                    } else if (cur > 0) {
                        ts = cur - 1;
                    } else {
                        if (lane == 0) { do { cur = atomicAdd(sp, 0); } while (cur <= 0); }
                        cur = __shfl_sync(FULL, cur, 0);
                        ts = cur - 1;
                    }

                    sm.p.m.sh[wl][lane]      = __ldcg(&g_h[ss * DIM + lane]);
                    sm.p.m.sh[wl][lane + 32] = __ldcg(&g_h[ss * DIM + lane + 32]);
                    __syncwarp();
                    float m0 = 0.f, m1 = 0.f, q0 = 0.f, q1 = 0.f;
                    #pragma unroll 8
                    for (int k = 0; k < DIM; k++) {
                        float hk = sm.p.m.sh[wl][k];
                        m0 = fmaf(hk, sm.p.m.M[k * DIM + lane],      m0);
                        m1 = fmaf(hk, sm.p.m.M[k * DIM + lane + 32], m1);
                        q0 = fmaf(hk, sm.p.m.G[k * DIM + lane],      q0);
                        q1 = fmaf(hk, sm.p.m.G[k * DIM + lane + 32], q1);
                    }
                    const float* rr = rele + (size_t)(l * NREL + r) * DIM;
                    float v0 = __ldg(&rr[lane])      * m0 * (1.f / (1.f + expf(-q0)));
                    float v1 = __ldg(&rr[lane + 32]) * m1 * (1.f / (1.f + expf(-q1)));
                    atomicAdd(&g_agg[ts * DIM + lane],      v0);
                    atomicAdd(&g_agg[ts * DIM + lane + 32], v1);
                    __syncwarp();
                }
            }
            // tail: preload NEXT layer's msg weights (hidden behind barrier wait
            // for idle blocks; two phases of slack before first use)
            __syncthreads();
            if (l + 1 < NLAYERS) {
                for (int i = tid; i < DIM * DIM; i += TPB) {
                    sm.p.m.M[i] = __ldg(&msgW[(l + 1) * DIM * DIM + i]);
                    sm.p.m.G[i] = __ldg(&gateW[(l + 1) * DIM * DIM + i]);
                }
            }
        }
        bar_n(2 + 2 * l, nlb);

        // ---- scan(l+1) (all layer warps) ----
        if (l + 1 < NLAYERS) scan_layer(esrc, l + 1, lwarp, lwarps, lane);

        // ---- update(l): TOP block range; weights already in sm.p.u ----
        // Last layer fuses the final score (stages result in g_actscore).
        {
            int total = __ldcg(&g_cnt[1]);
            int pb = min(nlb, max(1, (total + WPB - 1) / WPB));
            int b0 = nlb - pb;                  // top range [b0, nlb)
            if (bid >= b0) {
                float ub0 = __ldg(&updb[l * DIM + lane]), ub1 = __ldg(&updb[l * DIM + lane + 32]);
                float lg0 = __ldg(&lng[l * DIM + lane]),  lg1 = __ldg(&lng[l * DIM + lane + 32]);
                float lb0 = __ldg(&lnb[l * DIM + lane]),  lb1 = __ldg(&lnb[l * DIM + lane + 32]);
                float rb0 = __ldg(&sb1[lane]), rb1 = __ldg(&sb1[lane + 32]);
                float rv0 = __ldg(&sW2[lane]), rv1 = __ldg(&sW2[lane + 32]);
                float b2 = __ldg(&sb2[0]);
                for (int idx = (bid - b0) * WPB + wl; idx < total; idx += pb * WPB) {
                    int p = __ldcg(&g_nlist[idx]);
                    int n = p >> 2, b = p & 3;
                    int slot = __ldcg(&g_slotmap[b * NE + n]) - 1;
                    float h0 = __ldcg(&g_h[slot * DIM + lane]);
                    float h1 = __ldcg(&g_h[slot * DIM + lane + 32]);
                    float a0 = __ldcg(&g_agg[slot * DIM + lane]);
                    float a1 = __ldcg(&g_agg[slot * DIM + lane + 32]);
                    sm.p.u.x[wl][lane] = h0;      sm.p.u.x[wl][lane + 32] = h1;
                    sm.p.u.x[wl][64 + lane] = a0; sm.p.u.x[wl][96 + lane] = a1;
                    __syncwarp();
                    float u0 = ub0, u1 = ub1;
                    #pragma unroll 8
                    for (int k = 0; k < 2 * DIM; k++) {
                        float xk = sm.p.u.x[wl][k];
                        u0 = fmaf(xk, sm.p.u.W[k * DIM + lane],      u0);
                        u1 = fmaf(xk, sm.p.u.W[k * DIM + lane + 32], u1);
                    }
                    u0 = fmaxf(u0, 0.f); u1 = fmaxf(u1, 0.f);
                    float x0 = h0 + u0, x1 = h1 + u1;
                    float sums = x0 + x1;
                    #pragma unroll
                    for (int o = 16; o > 0; o >>= 1) sums += __shfl_xor_sync(FULL, sums, o);
                    float mean = sums * (1.f / 64.f);
                    float d0 = x0 - mean, d1 = x1 - mean;
                    float v = d0 * d0 + d1 * d1;
                    #pragma unroll
                    for (int o = 16; o > 0; o >>= 1) v += __shfl_xor_sync(FULL, v, o);
                    float inv = rsqrtf(v * (1.f / 64.f) + 1e-5f);
                    float nh0 = d0 * inv * lg0 + lb0;
                    float nh1 = d1 * inv * lg1 + lb1;
                    if (l < NLAYERS - 1) {
                        g_h[slot * DIM + lane]      = nh0;
                        g_h[slot * DIM + lane + 32] = nh1;
                        g_agg[slot * DIM + lane] = 0.f;
                        g_agg[slot * DIM + lane + 32] = 0.f;
                        __syncwarp();
                    } else {
                        // --- fused final score: [h_new, ent[n]] @ sW1 (L1-hot) ---
                        sm.p.u.x[wl][lane]      = nh0;
                        sm.p.u.x[wl][lane + 32] = nh1;
                        sm.p.u.x[wl][64 + lane] = __ldg(&ent[n * DIM + lane]);
                        sm.p.u.x[wl][96 + lane] = __ldg(&ent[n * DIM + lane + 32]);
                        __syncwarp();
                        float s0 = rb0, s1 = rb1;
                        #pragma unroll 8
                        for (int k = 0; k < 2 * DIM; k++) {
                            float xk = sm.p.u.x[wl][k];
                            s0 = fmaf(xk, __ldg(&sW1[k * DIM + lane]),      s0);
                            s1 = fmaf(xk, __ldg(&sW1[k * DIM + lane + 32]), s1);
                        }
                        float a = fmaxf(s0, 0.f) * rv0 + fmaxf(s1, 0.f) * rv1;
                        #pragma unroll
                        for (int o = 16; o > 0; o >>= 1) a += __shfl_xor_sync(FULL, a, o);
                        if (lane == 0) g_actscore[idx] = a + b2;
                        __syncwarp();
                    }
                }
            }
            // tail: preload NEXT layer's update weights
            __syncthreads();
            if (l + 1 < NLAYERS) {
                for (int i = tid; i < 2 * DIM * DIM; i += TPB)
                    sm.p.u.W[i] = __ldg(&updW[(l + 1) * 2 * DIM * DIM + i]);
            }
        }
        if (l < NLAYERS - 1) bar_n(3 + 2 * l, nlb);   // last layer: bar8 is the join
    }

    // ---------------- join, scatter+clean --------------------------------------
    {
        bar_n(8, nb);     // join: bg writes + staged scores visible everywhere
        int nAct = __ldcg(&g_cnt[1]);
        scatter_and_clean(out, nAct, gt, gthreads);
    }

    // ---------------- final barrier (ALL blocks) + counter reset --------------
    __syncthreads();
    if (tid == 0) {
        __threadfence();
        atomicAdd(&g_bar[9], 1u);
    }
    if (bid == 0 && tid == 0) {
        while (*(volatile unsigned int*)&g_bar[9] < (unsigned)nb) __nanosleep(64);
        #pragma unroll
        for (int i = 0; i < 16; i++) g_bar[i] = 0u;
        #pragma unroll
        for (int i = 0; i < 8; i++) g_cnt[i] = 0;
    }
}

extern "C" void kernel_launch(void* const* d_in, const int* in_sizes, int n_in,
                              void* d_out, int out_size) {
    const float* ent   = (const float*)d_in[0];
    const float* qemb  = (const float*)d_in[1];
    const float* rele  = (const float*)d_in[2];
    const float* msgW  = (const float*)d_in[3];
    const float* gateW = (const float*)d_in[4];
    const float* updW  = (const float*)d_in[5];
    const float* updb  = (const float*)d_in[6];
    const float* lng   = (const float*)d_in[7];
    const float* lnb   = (const float*)d_in[8];
    const float* sW1   = (const float*)d_in[9];
    const float* sb1   = (const float*)d_in[10];
    const float* sW2   = (const float*)d_in[11];
    const float* sb2   = (const float*)d_in[12];
    const int* source  = (const int*)d_in[13];
    const int* qrel    = (const int*)d_in[14];
    const int* esrc    = (const int*)d_in[15];
    const int* etgt    = (const int*)d_in[16];
    const int* erel    = (const int*)d_in[17];
    float* out = (float*)d_out;

    const int smemBytes = (int)sizeof(SMemAll);   // ~70 KB (de-unioned pipe)
    cudaFuncSetAttribute(k_all, cudaFuncAttributeMaxDynamicSharedMemorySize, smemBytes);

    int dev = 0;
    cudaGetDevice(&dev);
    int sms = 0;
    cudaDeviceGetAttribute(&sms, cudaDevAttrMultiProcessorCount, dev);
    int maxb = 0;
    cudaOccupancyMaxActiveBlocksPerMultiprocessor(&maxb, k_all, TPB, smemBytes);
    if (maxb < 1) maxb = 1;
    if (maxb > 2) maxb = 2;      // keep the measured-good 2-block/SM shape
    int grid = sms * maxb;

    k_all<<<grid, TPB, smemBytes>>>(ent, qemb, rele, msgW, gateW, updW, updb, lng, lnb,
                                    sW1, sb1, sW2, sb2, source, qrel, esrc, etgt, erel, out);
}